// round 5
// baseline (speedup 1.0000x reference)
#include <cuda_runtime.h>
#include <cstdint>

// Problem constants
#define BATCH 32
#define SEQ   576
#define CH    768
#define NH    12
#define HD    64
#define MROWS (BATCH * SEQ)      // 18432
#define QKVC  (3 * CH)           // 2304
#define GRID24 24
#define BS4   4
#define NKC48 48                 // K chunks of 16 (K=768)

// ---------------------------------------------------------------------------
// Scratch (__device__ globals; no allocations allowed)
// ---------------------------------------------------------------------------
__device__ float g_qkv[(size_t)MROWS * QKVC];   // fp32 qkv (gemm1 out, row-major)
__device__ float g_xt [(size_t)MROWS * CH];     // x packed tf32 tiles
__device__ float g_wqt[(size_t)QKVC * CH];      // qkv_w packed tf32 tiles
__device__ float g_wpt[(size_t)CH * CH];        // proj_w packed tf32 tiles
__device__ float g_att[(size_t)MROWS * CH];     // attention out, packed tf32 tiles

__device__ __forceinline__ int block_idx_of(int p) {
    int i = p / GRID24;
    int j = p - i * GRID24;
    return (i >> 2) * (GRID24 / BS4) + (j >> 2);
}

// ---------------------------------------------------------------------------
// helpers
// ---------------------------------------------------------------------------
__device__ __forceinline__ void cp_async16(void* smem, const void* gmem) {
    uint32_t s = (uint32_t)__cvta_generic_to_shared(smem);
    asm volatile("cp.async.cg.shared.global [%0], [%1], 16;\n" :: "r"(s), "l"(gmem));
}
__device__ __forceinline__ void cp_commit() {
    asm volatile("cp.async.commit_group;\n");
}
template<int N>
__device__ __forceinline__ void cp_wait() {
    asm volatile("cp.async.wait_group %0;\n" :: "n"(N));
}
__device__ __forceinline__ uint32_t f2tf32(float f) {
    uint32_t u;
    asm("cvt.rna.tf32.f32 %0, %1;\n" : "=r"(u) : "f"(f));
    return u;
}
#define MMA_TF32(acc, a0,a1,a2,a3, b0,b1)                                      \
    asm volatile(                                                              \
        "mma.sync.aligned.m16n8k8.row.col.f32.tf32.tf32.f32 "                  \
        "{%0,%1,%2,%3}, {%4,%5,%6,%7}, {%8,%9}, {%0,%1,%2,%3};\n"              \
        : "+f"(acc[0]), "+f"(acc[1]), "+f"(acc[2]), "+f"(acc[3])               \
        : "r"(a0), "r"(a1), "r"(a2), "r"(a3), "r"(b0), "r"(b1))

// Fast exp on FMA pipe (deg-5 Taylor after range reduction).
__device__ __forceinline__ float fexp(float x) {
    x = fmaxf(x, -87.0f);
    float t = x * 1.44269504f;
    int   ei = __float2int_rn(t);
    float fn = (float)ei;
    float r  = fmaf(fn, -0.69314718f, x);
    float p  = 8.3333337e-3f;
    p = fmaf(p, r, 4.1666668e-2f);
    p = fmaf(p, r, 0.16666667f);
    p = fmaf(p, r, 0.5f);
    p = fmaf(p, r, 1.0f);
    p = fmaf(p, r, 1.0f);
    return p * __int_as_float((ei + 127) << 23);
}

// Packed-tile addressing: 128-row tiles, 16-col k-chunks, cols interleaved
// within each 8-col k8 group as 0,4,1,5,2,6,3,7 (so frag pairs are adjacent).
__device__ __forceinline__ size_t packed_addr(int row, int col) {
    int mt = row >> 7, rin = row & 127;
    int kc = col >> 4, cin = col & 15;
    int pos = (cin & 8) | (((cin & 3) << 1) | ((cin >> 2) & 1));
    return (((size_t)mt * NKC48 + kc) * 128 + rin) * 16 + pos;
}

// ---------------------------------------------------------------------------
// Pre-pass: fp32 row-major [nrows,768] -> tf32-rounded packed tiles
// ---------------------------------------------------------------------------
__global__ void pack_tf32(const float* __restrict__ src, float* __restrict__ dst,
                          int total4)
{
    int idx = blockIdx.x * blockDim.x + threadIdx.x;
    if (idx >= total4) return;
    int row = idx / (CH / 4);
    int c4  = (idx - row * (CH / 4)) * 4;
    float4 f = *(const float4*)(src + (size_t)row * CH + c4);
    dst[packed_addr(row, c4 + 0)] = __uint_as_float(f2tf32(f.x));
    dst[packed_addr(row, c4 + 1)] = __uint_as_float(f2tf32(f.y));
    dst[packed_addr(row, c4 + 2)] = __uint_as_float(f2tf32(f.z));
    dst[packed_addr(row, c4 + 3)] = __uint_as_float(f2tf32(f.w));
}

// ---------------------------------------------------------------------------
// TF32 GEMM on packed tiles: C[M,ncols] = A @ B^T + bias, K=768.
// 128x128x16 CTA tile, 8 warps (4m x 2n), warp tile 32x64, 3-stage cp.async.
// No cvt in mainloop; fragment loads are LDS.64 (interleaved layout).
// ---------------------------------------------------------------------------
#define GPAD 20
#define STAGE_F (128 * GPAD)          // floats per matrix per stage (2560)
#define GEMM_SMEM (3 * 2 * STAGE_F * 4)   // 61440 bytes

__global__ __launch_bounds__(256)
void gemm_tf32p(const float* __restrict__ At, const float* __restrict__ Bt,
                const float* __restrict__ bias, float* __restrict__ Cm, int ncols)
{
    extern __shared__ float smf[];

    const int tid  = threadIdx.x;
    const int wid  = tid >> 5;
    const int lane = tid & 31;
    const int g    = lane >> 2;
    const int t4   = lane & 3;
    const int wm   = (wid & 3) * 32;
    const int wn   = (wid >> 2) * 64;
    const int bx = blockIdx.x, by = blockIdx.y;

    const float* Ab = At + (size_t)by * NKC48 * 2048;
    const float* Bb = Bt + (size_t)bx * NKC48 * 2048;

    float acc[2][8][4];
#pragma unroll
    for (int mt = 0; mt < 2; mt++)
#pragma unroll
        for (int nt = 0; nt < 8; nt++)
#pragma unroll
            for (int r = 0; r < 4; r++) acc[mt][nt][r] = 0.f;

    auto issue = [&](int kc) {
        const int s = kc % 3;
        float* dA = smf + s * (2 * STAGE_F);
        float* dB = dA + STAGE_F;
        const float* sA = Ab + (size_t)kc * 2048;
        const float* sB = Bb + (size_t)kc * 2048;
#pragma unroll
        for (int i = 0; i < 2; i++) {
            int fi = tid + (i << 8);          // float4 index 0..511
            int r  = fi >> 2, c = (fi & 3) << 2;
            cp_async16(dA + r * GPAD + c, sA + fi * 4);
            cp_async16(dB + r * GPAD + c, sB + fi * 4);
        }
        cp_commit();
    };

    issue(0);
    issue(1);

    for (int kc = 0; kc < NKC48; kc++) {
        if (kc + 1 < NKC48) cp_wait<1>(); else cp_wait<0>();
        __syncthreads();
        if (kc + 2 < NKC48) issue(kc + 2);

        const float* A0 = smf + (kc % 3) * (2 * STAGE_F);
        const float* B0 = A0 + STAGE_F;

#pragma unroll
        for (int kk = 0; kk < 2; kk++) {
            const int ko = kk * 8 + 2 * t4;
            float2 a00 = *(const float2*)(A0 + (wm + g)      * GPAD + ko);
            float2 a01 = *(const float2*)(A0 + (wm + g + 8)  * GPAD + ko);
            float2 a10 = *(const float2*)(A0 + (wm + 16 + g) * GPAD + ko);
            float2 a11 = *(const float2*)(A0 + (wm + 24 + g) * GPAD + ko);
            uint32_t af0[4] = { __float_as_uint(a00.x), __float_as_uint(a01.x),
                                __float_as_uint(a00.y), __float_as_uint(a01.y) };
            uint32_t af1[4] = { __float_as_uint(a10.x), __float_as_uint(a11.x),
                                __float_as_uint(a10.y), __float_as_uint(a11.y) };
#pragma unroll
            for (int nt = 0; nt < 8; nt++) {
                float2 bL = *(const float2*)(B0 + (wn + nt * 8 + g) * GPAD + ko);
                uint32_t b0 = __float_as_uint(bL.x);
                uint32_t b1 = __float_as_uint(bL.y);
                MMA_TF32(acc[0][nt], af0[0], af0[1], af0[2], af0[3], b0, b1);
                MMA_TF32(acc[1][nt], af1[0], af1[1], af1[2], af1[3], b0, b1);
            }
        }
    }

    // Epilogue: bias + store
#pragma unroll
    for (int mt = 0; mt < 2; mt++) {
        const int row = by * 128 + wm + mt * 16 + g;
#pragma unroll
        for (int nt = 0; nt < 8; nt++) {
            const int col = bx * 128 + wn + nt * 8 + (t4 << 1);
            float bx0 = bias[col], bx1 = bias[col + 1];
            float2 v0, v1;
            v0.x = acc[mt][nt][0] + bx0; v0.y = acc[mt][nt][1] + bx1;
            v1.x = acc[mt][nt][2] + bx0; v1.y = acc[mt][nt][3] + bx1;
            *(float2*)(Cm + (size_t)row * ncols + col)       = v0;
            *(float2*)(Cm + (size_t)(row + 8) * ncols + col) = v1;
        }
    }
}

// ---------------------------------------------------------------------------
// Tensor-core block-causal flash attention (R3 + interleaved K tiles,
// packed-tile epilogue feeding GEMM2 directly).
// ---------------------------------------------------------------------------
#define LDSA 68

struct AttnSmem {
    float Ksb[64 * LDSA];   // K big  (interleaved cols per k8 group)
    float Kss[64 * LDSA];   // K small (interleaved)
    float Vt [64 * LDSA];   // V (plain col order)
    float Ps [64 * LDSA];   // P tile (plain)
    int   kbi[SEQ];
    int   kmin[9];
    int   maxbq;
};

__global__ __launch_bounds__(128)
void attn_tc(const float* __restrict__ qkv, float* __restrict__ attp)
{
    extern __shared__ char smraw[];
    AttnSmem& sm = *reinterpret_cast<AttnSmem*>(smraw);

    const int b = blockIdx.z, h = blockIdx.y, qt = blockIdx.x;
    const int tid = threadIdx.x, wid = tid >> 5, lane = tid & 31;
    const int g = lane >> 2, t4 = lane & 3;
    const int wm = wid * 16;

    for (int p = tid; p < SEQ; p += 128) sm.kbi[p] = block_idx_of(p);
    __syncthreads();
    if (tid < 9) {
        int mn = 1 << 30;
        for (int j = 0; j < 64; j++) mn = min(mn, sm.kbi[tid * 64 + j]);
        sm.kmin[tid] = mn;
    } else if (tid == 9) {
        int mx = -1;
        for (int j = 0; j < 64; j++) mx = max(mx, sm.kbi[qt * 64 + j]);
        sm.maxbq = mx;
    }
    __syncthreads();

    const int qr0 = qt * 64 + wm + g;
    const int bq0 = sm.kbi[qr0];
    const int bq1 = sm.kbi[qr0 + 8];
    const int maxbq = sm.maxbq;

    uint32_t qb[8][4], qs[8][4];
    {
        const float* Qp0 = qkv + (size_t)(b * SEQ + qr0) * QKVC + h * HD;
        const float* Qp1 = Qp0 + (size_t)8 * QKVC;
#pragma unroll
        for (int kk = 0; kk < 8; kk++) {
            float r0 = Qp0[kk * 8 + t4]     * 0.125f;
            float r1 = Qp1[kk * 8 + t4]     * 0.125f;
            float r2 = Qp0[kk * 8 + t4 + 4] * 0.125f;
            float r3 = Qp1[kk * 8 + t4 + 4] * 0.125f;
            qb[kk][0] = f2tf32(r0); qs[kk][0] = f2tf32(r0 - __uint_as_float(qb[kk][0]));
            qb[kk][1] = f2tf32(r1); qs[kk][1] = f2tf32(r1 - __uint_as_float(qb[kk][1]));
            qb[kk][2] = f2tf32(r2); qs[kk][2] = f2tf32(r2 - __uint_as_float(qb[kk][2]));
            qb[kk][3] = f2tf32(r3); qs[kk][3] = f2tf32(r3 - __uint_as_float(qb[kk][3]));
        }
    }

    float m0 = -1e30f, m1 = -1e30f, l0 = 0.f, l1 = 0.f;
    float o[8][4];
#pragma unroll
    for (int nt = 0; nt < 8; nt++)
#pragma unroll
        for (int r = 0; r < 4; r++) o[nt][r] = 0.f;

    for (int kt = 0; kt < 9; kt++) {
        if (sm.kmin[kt] > maxbq) continue;
        __syncthreads();

        // Load K (split big/small, interleaved cols) and V (tf32)
        {
            const float* Kg = qkv + (size_t)(b * SEQ + kt * 64) * QKVC + CH + h * HD;
            const float* Vg = Kg + CH;
#pragma unroll
            for (int i = 0; i < 8; i++) {
                int u = tid + i * 128;
                int r = u >> 4, c = (u & 15) << 2;   // c in {0,4,...,60}
                float4 k4 = *(const float4*)(Kg + (size_t)r * QKVC + c);
                float4 v4 = *(const float4*)(Vg + (size_t)r * QKVC + c);
                float b0 = __uint_as_float(f2tf32(k4.x));
                float b1 = __uint_as_float(f2tf32(k4.y));
                float b2 = __uint_as_float(f2tf32(k4.z));
                float b3 = __uint_as_float(f2tf32(k4.w));
                float s0 = __uint_as_float(f2tf32(k4.x - b0));
                float s1 = __uint_as_float(f2tf32(k4.y - b1));
                float s2 = __uint_as_float(f2tf32(k4.z - b2));
                float s3 = __uint_as_float(f2tf32(k4.w - b3));
                // interleaved positions within the 8-col group
                int base = r * LDSA + (c & 56);       // group*8
                int pb   = (c >> 2) & 1;              // 0 for c%8==0, 1 for c%8==4
                sm.Ksb[base + pb]     = b0;
                sm.Ksb[base + pb + 2] = b1;
                sm.Ksb[base + pb + 4] = b2;
                sm.Ksb[base + pb + 6] = b3;
                sm.Kss[base + pb]     = s0;
                sm.Kss[base + pb + 2] = s1;
                sm.Kss[base + pb + 4] = s2;
                sm.Kss[base + pb + 6] = s3;
                float4 vt;
                vt.x = __uint_as_float(f2tf32(v4.x));
                vt.y = __uint_as_float(f2tf32(v4.y));
                vt.z = __uint_as_float(f2tf32(v4.z));
                vt.w = __uint_as_float(f2tf32(v4.w));
                *(float4*)&sm.Vt[r * LDSA + c] = vt;
            }
        }
        __syncthreads();

        // S = Q K^T (3x tf32 split); K frag pairs via LDS.64
        float sacc[8][4];
#pragma unroll
        for (int nt = 0; nt < 8; nt++)
#pragma unroll
            for (int r = 0; r < 4; r++) sacc[nt][r] = 0.f;

#pragma unroll
        for (int kk = 0; kk < 8; kk++) {
            const int ko = kk * 8 + 2 * t4;
#pragma unroll
            for (int nt = 0; nt < 8; nt++) {
                float2 hb = *(const float2*)&sm.Ksb[(nt * 8 + g) * LDSA + ko];
                float2 sb = *(const float2*)&sm.Kss[(nt * 8 + g) * LDSA + ko];
                uint32_t bb0 = __float_as_uint(hb.x);
                uint32_t bb1 = __float_as_uint(hb.y);
                uint32_t bs0 = __float_as_uint(sb.x);
                uint32_t bs1 = __float_as_uint(sb.y);
                MMA_TF32(sacc[nt], qb[kk][0], qb[kk][1], qb[kk][2], qb[kk][3], bb0, bb1);
                MMA_TF32(sacc[nt], qb[kk][0], qb[kk][1], qb[kk][2], qb[kk][3], bs0, bs1);
                MMA_TF32(sacc[nt], qs[kk][0], qs[kk][1], qs[kk][2], qs[kk][3], bb0, bb1);
            }
        }

        const int c0 = kt * 64;
        int kbl[16];
#pragma unroll
        for (int nt = 0; nt < 8; nt++) {
            kbl[nt * 2]     = sm.kbi[c0 + nt * 8 + 2 * t4];
            kbl[nt * 2 + 1] = sm.kbi[c0 + nt * 8 + 2 * t4 + 1];
        }
#pragma unroll
        for (int nt = 0; nt < 8; nt++) {
            if (kbl[nt * 2]     > bq0) sacc[nt][0] = -1e30f;
            if (kbl[nt * 2 + 1] > bq0) sacc[nt][1] = -1e30f;
            if (kbl[nt * 2]     > bq1) sacc[nt][2] = -1e30f;
            if (kbl[nt * 2 + 1] > bq1) sacc[nt][3] = -1e30f;
        }

        float mx0 = -1e30f, mx1 = -1e30f;
#pragma unroll
        for (int nt = 0; nt < 8; nt++) {
            mx0 = fmaxf(mx0, fmaxf(sacc[nt][0], sacc[nt][1]));
            mx1 = fmaxf(mx1, fmaxf(sacc[nt][2], sacc[nt][3]));
        }
        mx0 = fmaxf(mx0, __shfl_xor_sync(0xffffffffu, mx0, 1));
        mx0 = fmaxf(mx0, __shfl_xor_sync(0xffffffffu, mx0, 2));
        mx1 = fmaxf(mx1, __shfl_xor_sync(0xffffffffu, mx1, 1));
        mx1 = fmaxf(mx1, __shfl_xor_sync(0xffffffffu, mx1, 2));

        float nm0 = fmaxf(m0, mx0), nm1 = fmaxf(m1, mx1);
        float cr0 = fexp(m0 - nm0), cr1 = fexp(m1 - nm1);
        m0 = nm0; m1 = nm1;
        l0 *= cr0; l1 *= cr1;
#pragma unroll
        for (int nt = 0; nt < 8; nt++) {
            o[nt][0] *= cr0; o[nt][1] *= cr0;
            o[nt][2] *= cr1; o[nt][3] *= cr1;
        }

        float s0 = 0.f, s1 = 0.f;
        float* pr0 = &sm.Ps[(size_t)(wm + g) * LDSA];
        float* pr1 = &sm.Ps[(size_t)(wm + g + 8) * LDSA];
#pragma unroll
        for (int nt = 0; nt < 8; nt++) {
            float p0 = (sacc[nt][0] > -1e29f) ? fexp(sacc[nt][0] - nm0) : 0.f;
            float p1 = (sacc[nt][1] > -1e29f) ? fexp(sacc[nt][1] - nm0) : 0.f;
            float p2 = (sacc[nt][2] > -1e29f) ? fexp(sacc[nt][2] - nm1) : 0.f;
            float p3 = (sacc[nt][3] > -1e29f) ? fexp(sacc[nt][3] - nm1) : 0.f;
            p0 = __uint_as_float(f2tf32(p0));
            p1 = __uint_as_float(f2tf32(p1));
            p2 = __uint_as_float(f2tf32(p2));
            p3 = __uint_as_float(f2tf32(p3));
            s0 += p0 + p1; s1 += p2 + p3;
            float2 w0; w0.x = p0; w0.y = p1;
            float2 w1; w1.x = p2; w1.y = p3;
            *(float2*)(pr0 + nt * 8 + 2 * t4) = w0;
            *(float2*)(pr1 + nt * 8 + 2 * t4) = w1;
        }
        s0 += __shfl_xor_sync(0xffffffffu, s0, 1);
        s0 += __shfl_xor_sync(0xffffffffu, s0, 2);
        s1 += __shfl_xor_sync(0xffffffffu, s1, 1);
        s1 += __shfl_xor_sync(0xffffffffu, s1, 2);
        l0 += s0; l1 += s1;
        __syncwarp();

#pragma unroll
        for (int kk = 0; kk < 8; kk++) {
            uint32_t a0 = __float_as_uint(sm.Ps[(wm + g) * LDSA + kk * 8 + t4]);
            uint32_t a1 = __float_as_uint(sm.Ps[(wm + g + 8) * LDSA + kk * 8 + t4]);
            uint32_t a2 = __float_as_uint(sm.Ps[(wm + g) * LDSA + kk * 8 + t4 + 4]);
            uint32_t a3 = __float_as_uint(sm.Ps[(wm + g + 8) * LDSA + kk * 8 + t4 + 4]);
#pragma unroll
            for (int nt = 0; nt < 8; nt++) {
                uint32_t b0v = __float_as_uint(sm.Vt[(kk * 8 + t4) * LDSA + nt * 8 + g]);
                uint32_t b1v = __float_as_uint(sm.Vt[(kk * 8 + t4 + 4) * LDSA + nt * 8 + g]);
                MMA_TF32(o[nt], a0, a1, a2, a3, b0v, b1v);
            }
        }
        __syncwarp();
    }

    // Epilogue: normalize, tf32-round, write packed tiles for GEMM2's A side
    const float inv0 = 1.f / l0, inv1 = 1.f / l1;
    const int qrow0 = b * SEQ + qr0;
    const int qrow1 = qrow0 + 8;
#pragma unroll
    for (int nt = 0; nt < 8; nt++) {
        int col = h * HD + nt * 8 + 2 * t4;
        attp[packed_addr(qrow0, col)]     = __uint_as_float(f2tf32(o[nt][0] * inv0));
        attp[packed_addr(qrow0, col + 1)] = __uint_as_float(f2tf32(o[nt][1] * inv0));
        attp[packed_addr(qrow1, col)]     = __uint_as_float(f2tf32(o[nt][2] * inv1));
        attp[packed_addr(qrow1, col + 1)] = __uint_as_float(f2tf32(o[nt][3] * inv1));
    }
}

// ---------------------------------------------------------------------------
// Launch: pack x/weights -> gemm1 -> attention -> gemm2
// ---------------------------------------------------------------------------
extern "C" void kernel_launch(void* const* d_in, const int* in_sizes, int n_in,
                              void* d_out, int out_size)
{
    const float* x      = (const float*)d_in[0];
    const float* qkv_w  = (const float*)d_in[1];
    const float* qkv_b  = (const float*)d_in[2];
    const float* proj_w = (const float*)d_in[3];
    const float* proj_b = (const float*)d_in[4];
    float* out = (float*)d_out;

    float *qkvbuf, *xt, *wqt, *wpt, *attp;
    cudaGetSymbolAddress((void**)&qkvbuf, g_qkv);
    cudaGetSymbolAddress((void**)&xt,   g_xt);
    cudaGetSymbolAddress((void**)&wqt,  g_wqt);
    cudaGetSymbolAddress((void**)&wpt,  g_wpt);
    cudaGetSymbolAddress((void**)&attp, g_att);

    cudaFuncSetAttribute(gemm_tf32p, cudaFuncAttributeMaxDynamicSharedMemorySize,
                         GEMM_SMEM);
    cudaFuncSetAttribute(attn_tc, cudaFuncAttributeMaxDynamicSharedMemorySize,
                         (int)sizeof(AttnSmem));

    // Pre-pass: pack + tf32-round
    pack_tf32<<<(MROWS * (CH / 4) + 255) / 256, 256>>>(x, xt, MROWS * (CH / 4));
    pack_tf32<<<(QKVC  * (CH / 4) + 255) / 256, 256>>>(qkv_w, wqt, QKVC * (CH / 4));
    pack_tf32<<<(CH    * (CH / 4) + 255) / 256, 256>>>(proj_w, wpt, CH * (CH / 4));

    // 1) qkv = x @ qkv_w^T + qkv_b   (M=18432, N=2304)
    dim3 g1(QKVC / 128, MROWS / 128);    // (18, 144)
    gemm_tf32p<<<g1, 256, GEMM_SMEM>>>(xt, wqt, qkv_b, qkvbuf, QKVC);

    // 2) block-causal attention -> packed tf32 tiles
    dim3 g2(SEQ / 64, NH, BATCH);        // (9, 12, 32)
    attn_tc<<<g2, 128, (int)sizeof(AttnSmem)>>>(qkvbuf, attp);

    // 3) out = att @ proj_w^T + proj_b  (M=18432, N=768)
    dim3 g3(CH / 128, MROWS / 128);      // (6, 144)
    gemm_tf32p<<<g3, 256, GEMM_SMEM>>>(attp, wpt, proj_b, out, CH);
}

// round 6
// speedup vs baseline: 1.6673x; 1.6673x over previous
#include <cuda_runtime.h>
#include <cuda_fp16.h>
#include <cstdint>

// Problem constants
#define BATCH 32
#define SEQ   576
#define CH    768
#define NH    12
#define HD    64
#define MROWS (BATCH * SEQ)      // 18432
#define QKVC  (3 * CH)           // 2304
#define GRID24 24
#define BS4   4

// ---------------------------------------------------------------------------
// Scratch (__device__ globals; no allocations allowed)
// ---------------------------------------------------------------------------
__device__ float  g_qkv[(size_t)MROWS * QKVC];   // fp32 qkv (gemm1 out)
__device__ __half g_xh [(size_t)MROWS * CH];     // x fp16
__device__ __half g_wqh[(size_t)QKVC * CH];      // qkv_w fp16
__device__ __half g_wph[(size_t)CH * CH];        // proj_w fp16
__device__ __half g_ath[(size_t)MROWS * CH];     // attention out fp16

__device__ __forceinline__ int block_idx_of(int p) {
    int i = p / GRID24;
    int j = p - i * GRID24;
    return (i >> 2) * (GRID24 / BS4) + (j >> 2);
}

// ---------------------------------------------------------------------------
// helpers
// ---------------------------------------------------------------------------
__device__ __forceinline__ void cp_async16(void* smem, const void* gmem) {
    uint32_t s = (uint32_t)__cvta_generic_to_shared(smem);
    asm volatile("cp.async.cg.shared.global [%0], [%1], 16;\n" :: "r"(s), "l"(gmem));
}
__device__ __forceinline__ void cp_commit() {
    asm volatile("cp.async.commit_group;\n");
}
template<int N>
__device__ __forceinline__ void cp_wait() {
    asm volatile("cp.async.wait_group %0;\n" :: "n"(N));
}
__device__ __forceinline__ uint32_t f2tf32(float f) {
    uint32_t u;
    asm("cvt.rna.tf32.f32 %0, %1;\n" : "=r"(u) : "f"(f));
    return u;
}
__device__ __forceinline__ uint32_t smem_u32(const void* p) {
    uint32_t a;
    asm("{ .reg .u64 t; cvta.to.shared.u64 t, %1; cvt.u32.u64 %0, t; }" : "=r"(a) : "l"(p));
    return a;
}
#define LDMATRIX_X4(r0, r1, r2, r3, addr)                                       \
    asm volatile("ldmatrix.sync.aligned.m8n8.x4.shared.b16 {%0,%1,%2,%3}, [%4];" \
                 : "=r"(r0), "=r"(r1), "=r"(r2), "=r"(r3) : "r"(addr))

#define MMA_F16(acc, a0,a1,a2,a3, b0,b1)                                        \
    asm volatile(                                                               \
        "mma.sync.aligned.m16n8k16.row.col.f32.f16.f16.f32 "                    \
        "{%0,%1,%2,%3}, {%4,%5,%6,%7}, {%8,%9}, {%0,%1,%2,%3};\n"               \
        : "+f"(acc[0]), "+f"(acc[1]), "+f"(acc[2]), "+f"(acc[3])                \
        : "r"(a0), "r"(a1), "r"(a2), "r"(a3), "r"(b0), "r"(b1))

#define MMA_TF32(acc, a0,a1,a2,a3, b0,b1)                                       \
    asm volatile(                                                               \
        "mma.sync.aligned.m16n8k8.row.col.f32.tf32.tf32.f32 "                   \
        "{%0,%1,%2,%3}, {%4,%5,%6,%7}, {%8,%9}, {%0,%1,%2,%3};\n"               \
        : "+f"(acc[0]), "+f"(acc[1]), "+f"(acc[2]), "+f"(acc[3])                \
        : "r"(a0), "r"(a1), "r"(a2), "r"(a3), "r"(b0), "r"(b1))

// Fast exp on FMA pipe
__device__ __forceinline__ float fexp(float x) {
    x = fmaxf(x, -87.0f);
    float t = x * 1.44269504f;
    int   ei = __float2int_rn(t);
    float fn = (float)ei;
    float r  = fmaf(fn, -0.69314718f, x);
    float p  = 8.3333337e-3f;
    p = fmaf(p, r, 4.1666668e-2f);
    p = fmaf(p, r, 0.16666667f);
    p = fmaf(p, r, 0.5f);
    p = fmaf(p, r, 1.0f);
    p = fmaf(p, r, 1.0f);
    return p * __int_as_float((ei + 127) << 23);
}

// ---------------------------------------------------------------------------
// Pre-pass: fp32 row-major -> fp16 row-major
// ---------------------------------------------------------------------------
__global__ void pack_half(const float* __restrict__ src, __half* __restrict__ dst,
                          int total4)
{
    int idx = blockIdx.x * blockDim.x + threadIdx.x;
    if (idx >= total4) return;
    float4 f = *(const float4*)(src + (size_t)idx * 4);
    __half2 h01 = __floats2half2_rn(f.x, f.y);
    __half2 h23 = __floats2half2_rn(f.z, f.w);
    ((__half2*)dst)[idx * 2]     = h01;
    ((__half2*)dst)[idx * 2 + 1] = h23;
}

// ---------------------------------------------------------------------------
// FP16 tensor-core GEMM (NT): C[M,ncols] = A[M,K] @ B[N,K]^T + bias, K=768.
// 128x128x32 CTA tile, 8 warps (4m x 2n), warp tile 32x64,
// mma.sync.m16n8k16.f16 (fp32 accum), ldmatrix fragments, double buffer.
// ---------------------------------------------------------------------------
#define BKH 32
#define LDH 40   // padded half stride (80B) -> conflict-free ldmatrix

__global__ __launch_bounds__(256)
void gemm_fp16(const __half* __restrict__ A, const __half* __restrict__ Bm,
               const float* __restrict__ bias, float* __restrict__ Cm,
               int ncols, int Kd)
{
    __shared__ __half As[2][128 * LDH];
    __shared__ __half Bs[2][128 * LDH];

    const int tid  = threadIdx.x;
    const int wid  = tid >> 5;
    const int lane = tid & 31;
    const int g    = lane >> 2;
    const int t4   = lane & 3;
    const int wm   = (wid & 3) * 32;
    const int wn   = (wid >> 2) * 64;
    const int bx = blockIdx.x, by = blockIdx.y;

    const __half* Ag = A  + (size_t)(by * 128) * Kd;
    const __half* Bg = Bm + (size_t)(bx * 128) * Kd;

    float acc[2][8][4];
#pragma unroll
    for (int mt = 0; mt < 2; mt++)
#pragma unroll
        for (int nt = 0; nt < 8; nt++)
#pragma unroll
            for (int r = 0; r < 4; r++) acc[mt][nt][r] = 0.f;

    // ldmatrix lane address components
    const int a_row = (lane & 7) + ((lane >> 3) & 1) * 8;   // A: row within 16
    const int a_ch  = ((lane >> 4) & 1) * 8;                // A: k-half
    const int b_row = (lane & 7) + ((lane >> 4) & 1) * 8;   // B: n within 16
    const int b_ch  = ((lane >> 3) & 1) * 8;                // B: k-half

    const int nk = Kd / BKH;   // 24

    auto issue = [&](int kt, int s) {
        const int k0 = kt * BKH;
#pragma unroll
        for (int i = 0; i < 2; i++) {
            int fi = tid + (i << 8);         // 0..511
            int r  = fi >> 2;                // row 0..127
            int c  = (fi & 3) << 3;          // half-col {0,8,16,24}
            cp_async16(&As[s][r * LDH + c], Ag + (size_t)r * Kd + k0 + c);
            cp_async16(&Bs[s][r * LDH + c], Bg + (size_t)r * Kd + k0 + c);
        }
        cp_commit();
    };

    issue(0, 0);

    for (int kt = 0; kt < nk; kt++) {
        const int s = kt & 1;
        if (kt + 1 < nk) {
            issue(kt + 1, s ^ 1);
            cp_wait<1>();
        } else {
            cp_wait<0>();
        }
        __syncthreads();

#pragma unroll
        for (int kk = 0; kk < 2; kk++) {      // two k16 steps
            const int k0 = kk * 16;
            uint32_t af[2][4];
#pragma unroll
            for (int mt = 0; mt < 2; mt++) {
                uint32_t addr = smem_u32(&As[s][(wm + mt * 16 + a_row) * LDH + k0 + a_ch]);
                LDMATRIX_X4(af[mt][0], af[mt][1], af[mt][2], af[mt][3], addr);
            }
#pragma unroll
            for (int np = 0; np < 4; np++) {  // n16 pairs
                uint32_t b0, b1, b2, b3;
                uint32_t addr = smem_u32(&Bs[s][(wn + np * 16 + b_row) * LDH + k0 + b_ch]);
                LDMATRIX_X4(b0, b1, b2, b3, addr);
#pragma unroll
                for (int mt = 0; mt < 2; mt++) {
                    MMA_F16(acc[mt][np * 2],     af[mt][0], af[mt][1], af[mt][2], af[mt][3], b0, b1);
                    MMA_F16(acc[mt][np * 2 + 1], af[mt][0], af[mt][1], af[mt][2], af[mt][3], b2, b3);
                }
            }
        }
        __syncthreads();
    }

    // Epilogue: bias + store
#pragma unroll
    for (int mt = 0; mt < 2; mt++) {
        const int row = by * 128 + wm + mt * 16 + g;
#pragma unroll
        for (int nt = 0; nt < 8; nt++) {
            const int col = bx * 128 + wn + nt * 8 + (t4 << 1);
            float bx0 = bias[col], bx1 = bias[col + 1];
            float2 v0, v1;
            v0.x = acc[mt][nt][0] + bx0; v0.y = acc[mt][nt][1] + bx1;
            v1.x = acc[mt][nt][2] + bx0; v1.y = acc[mt][nt][3] + bx1;
            *(float2*)(Cm + (size_t)row * ncols + col)       = v0;
            *(float2*)(Cm + (size_t)(row + 8) * ncols + col) = v1;
        }
    }
}

// ---------------------------------------------------------------------------
// Tensor-core block-causal flash attention (round-3-passing version; epilogue
// now writes fp16 for GEMM2).
// ---------------------------------------------------------------------------
#define LDSA 68

struct AttnSmem {
    float Ksb[64 * LDSA];
    float Kss[64 * LDSA];
    float Vt [64 * LDSA];
    float Ps [64 * LDSA];
    int   kbi[SEQ];
    int   kmin[9];
    int   maxbq;
};

__global__ __launch_bounds__(128)
void attn_tc(const float* __restrict__ qkv, __half* __restrict__ atth)
{
    extern __shared__ char smraw[];
    AttnSmem& sm = *reinterpret_cast<AttnSmem*>(smraw);

    const int b = blockIdx.z, h = blockIdx.y, qt = blockIdx.x;
    const int tid = threadIdx.x, wid = tid >> 5, lane = tid & 31;
    const int g = lane >> 2, t4 = lane & 3;
    const int wm = wid * 16;

    for (int p = tid; p < SEQ; p += 128) sm.kbi[p] = block_idx_of(p);
    __syncthreads();
    if (tid < 9) {
        int mn = 1 << 30;
        for (int j = 0; j < 64; j++) mn = min(mn, sm.kbi[tid * 64 + j]);
        sm.kmin[tid] = mn;
    } else if (tid == 9) {
        int mx = -1;
        for (int j = 0; j < 64; j++) mx = max(mx, sm.kbi[qt * 64 + j]);
        sm.maxbq = mx;
    }
    __syncthreads();

    const int qr0 = qt * 64 + wm + g;
    const int bq0 = sm.kbi[qr0];
    const int bq1 = sm.kbi[qr0 + 8];
    const int maxbq = sm.maxbq;

    uint32_t qb[8][4], qs[8][4];
    {
        const float* Qp0 = qkv + (size_t)(b * SEQ + qr0) * QKVC + h * HD;
        const float* Qp1 = Qp0 + (size_t)8 * QKVC;
#pragma unroll
        for (int kk = 0; kk < 8; kk++) {
            float r0 = Qp0[kk * 8 + t4]     * 0.125f;
            float r1 = Qp1[kk * 8 + t4]     * 0.125f;
            float r2 = Qp0[kk * 8 + t4 + 4] * 0.125f;
            float r3 = Qp1[kk * 8 + t4 + 4] * 0.125f;
            qb[kk][0] = f2tf32(r0); qs[kk][0] = f2tf32(r0 - __uint_as_float(qb[kk][0]));
            qb[kk][1] = f2tf32(r1); qs[kk][1] = f2tf32(r1 - __uint_as_float(qb[kk][1]));
            qb[kk][2] = f2tf32(r2); qs[kk][2] = f2tf32(r2 - __uint_as_float(qb[kk][2]));
            qb[kk][3] = f2tf32(r3); qs[kk][3] = f2tf32(r3 - __uint_as_float(qb[kk][3]));
        }
    }

    float m0 = -1e30f, m1 = -1e30f, l0 = 0.f, l1 = 0.f;
    float o[8][4];
#pragma unroll
    for (int nt = 0; nt < 8; nt++)
#pragma unroll
        for (int r = 0; r < 4; r++) o[nt][r] = 0.f;

    for (int kt = 0; kt < 9; kt++) {
        if (sm.kmin[kt] > maxbq) continue;
        __syncthreads();

        {
            const float* Kg = qkv + (size_t)(b * SEQ + kt * 64) * QKVC + CH + h * HD;
            const float* Vg = Kg + CH;
#pragma unroll
            for (int i = 0; i < 8; i++) {
                int u = tid + i * 128;
                int r = u >> 4, c = (u & 15) << 2;
                float4 k4 = *(const float4*)(Kg + (size_t)r * QKVC + c);
                float4 v4 = *(const float4*)(Vg + (size_t)r * QKVC + c);
                uint32_t kb0 = f2tf32(k4.x), kb1 = f2tf32(k4.y);
                uint32_t kb2 = f2tf32(k4.z), kb3 = f2tf32(k4.w);
                float4 big, sml, vt;
                big.x = __uint_as_float(kb0); big.y = __uint_as_float(kb1);
                big.z = __uint_as_float(kb2); big.w = __uint_as_float(kb3);
                sml.x = __uint_as_float(f2tf32(k4.x - big.x));
                sml.y = __uint_as_float(f2tf32(k4.y - big.y));
                sml.z = __uint_as_float(f2tf32(k4.z - big.z));
                sml.w = __uint_as_float(f2tf32(k4.w - big.w));
                vt.x = __uint_as_float(f2tf32(v4.x));
                vt.y = __uint_as_float(f2tf32(v4.y));
                vt.z = __uint_as_float(f2tf32(v4.z));
                vt.w = __uint_as_float(f2tf32(v4.w));
                *(float4*)&sm.Ksb[r * LDSA + c] = big;
                *(float4*)&sm.Kss[r * LDSA + c] = sml;
                *(float4*)&sm.Vt [r * LDSA + c] = vt;
            }
        }
        __syncthreads();

        float sacc[8][4];
#pragma unroll
        for (int nt = 0; nt < 8; nt++)
#pragma unroll
            for (int r = 0; r < 4; r++) sacc[nt][r] = 0.f;

#pragma unroll
        for (int kk = 0; kk < 8; kk++) {
#pragma unroll
            for (int nt = 0; nt < 8; nt++) {
                const float* kbp = &sm.Ksb[(nt * 8 + g) * LDSA + kk * 8];
                const float* ksp = &sm.Kss[(nt * 8 + g) * LDSA + kk * 8];
                uint32_t bb0 = __float_as_uint(kbp[t4]);
                uint32_t bb1 = __float_as_uint(kbp[t4 + 4]);
                uint32_t bs0 = __float_as_uint(ksp[t4]);
                uint32_t bs1 = __float_as_uint(ksp[t4 + 4]);
                MMA_TF32(sacc[nt], qb[kk][0], qb[kk][1], qb[kk][2], qb[kk][3], bb0, bb1);
                MMA_TF32(sacc[nt], qb[kk][0], qb[kk][1], qb[kk][2], qb[kk][3], bs0, bs1);
                MMA_TF32(sacc[nt], qs[kk][0], qs[kk][1], qs[kk][2], qs[kk][3], bb0, bb1);
            }
        }

        const int c0 = kt * 64;
        int kbl[16];
#pragma unroll
        for (int nt = 0; nt < 8; nt++) {
            kbl[nt * 2]     = sm.kbi[c0 + nt * 8 + 2 * t4];
            kbl[nt * 2 + 1] = sm.kbi[c0 + nt * 8 + 2 * t4 + 1];
        }
#pragma unroll
        for (int nt = 0; nt < 8; nt++) {
            if (kbl[nt * 2]     > bq0) sacc[nt][0] = -1e30f;
            if (kbl[nt * 2 + 1] > bq0) sacc[nt][1] = -1e30f;
            if (kbl[nt * 2]     > bq1) sacc[nt][2] = -1e30f;
            if (kbl[nt * 2 + 1] > bq1) sacc[nt][3] = -1e30f;
        }

        float mx0 = -1e30f, mx1 = -1e30f;
#pragma unroll
        for (int nt = 0; nt < 8; nt++) {
            mx0 = fmaxf(mx0, fmaxf(sacc[nt][0], sacc[nt][1]));
            mx1 = fmaxf(mx1, fmaxf(sacc[nt][2], sacc[nt][3]));
        }
        mx0 = fmaxf(mx0, __shfl_xor_sync(0xffffffffu, mx0, 1));
        mx0 = fmaxf(mx0, __shfl_xor_sync(0xffffffffu, mx0, 2));
        mx1 = fmaxf(mx1, __shfl_xor_sync(0xffffffffu, mx1, 1));
        mx1 = fmaxf(mx1, __shfl_xor_sync(0xffffffffu, mx1, 2));

        float nm0 = fmaxf(m0, mx0), nm1 = fmaxf(m1, mx1);
        float cr0 = fexp(m0 - nm0), cr1 = fexp(m1 - nm1);
        m0 = nm0; m1 = nm1;
        l0 *= cr0; l1 *= cr1;
#pragma unroll
        for (int nt = 0; nt < 8; nt++) {
            o[nt][0] *= cr0; o[nt][1] *= cr0;
            o[nt][2] *= cr1; o[nt][3] *= cr1;
        }

        float s0 = 0.f, s1 = 0.f;
        float* pr0 = &sm.Ps[(size_t)(wm + g) * LDSA];
        float* pr1 = &sm.Ps[(size_t)(wm + g + 8) * LDSA];
#pragma unroll
        for (int nt = 0; nt < 8; nt++) {
            float p0 = (sacc[nt][0] > -1e29f) ? fexp(sacc[nt][0] - nm0) : 0.f;
            float p1 = (sacc[nt][1] > -1e29f) ? fexp(sacc[nt][1] - nm0) : 0.f;
            float p2 = (sacc[nt][2] > -1e29f) ? fexp(sacc[nt][2] - nm1) : 0.f;
            float p3 = (sacc[nt][3] > -1e29f) ? fexp(sacc[nt][3] - nm1) : 0.f;
            p0 = __uint_as_float(f2tf32(p0));
            p1 = __uint_as_float(f2tf32(p1));
            p2 = __uint_as_float(f2tf32(p2));
            p3 = __uint_as_float(f2tf32(p3));
            s0 += p0 + p1; s1 += p2 + p3;
            float2 w0; w0.x = p0; w0.y = p1;
            float2 w1; w1.x = p2; w1.y = p3;
            *(float2*)(pr0 + nt * 8 + 2 * t4) = w0;
            *(float2*)(pr1 + nt * 8 + 2 * t4) = w1;
        }
        s0 += __shfl_xor_sync(0xffffffffu, s0, 1);
        s0 += __shfl_xor_sync(0xffffffffu, s0, 2);
        s1 += __shfl_xor_sync(0xffffffffu, s1, 1);
        s1 += __shfl_xor_sync(0xffffffffu, s1, 2);
        l0 += s0; l1 += s1;
        __syncwarp();

#pragma unroll
        for (int kk = 0; kk < 8; kk++) {
            uint32_t a0 = __float_as_uint(sm.Ps[(wm + g) * LDSA + kk * 8 + t4]);
            uint32_t a1 = __float_as_uint(sm.Ps[(wm + g + 8) * LDSA + kk * 8 + t4]);
            uint32_t a2 = __float_as_uint(sm.Ps[(wm + g) * LDSA + kk * 8 + t4 + 4]);
            uint32_t a3 = __float_as_uint(sm.Ps[(wm + g + 8) * LDSA + kk * 8 + t4 + 4]);
#pragma unroll
            for (int nt = 0; nt < 8; nt++) {
                uint32_t b0v = __float_as_uint(sm.Vt[(kk * 8 + t4) * LDSA + nt * 8 + g]);
                uint32_t b1v = __float_as_uint(sm.Vt[(kk * 8 + t4 + 4) * LDSA + nt * 8 + g]);
                MMA_TF32(o[nt], a0, a1, a2, a3, b0v, b1v);
            }
        }
        __syncwarp();
    }

    // Epilogue: normalize + store fp16 (feeds GEMM2 directly)
    const float inv0 = 1.f / l0, inv1 = 1.f / l1;
    __half* Or0 = atth + (size_t)(b * SEQ + qr0) * CH + h * HD;
    __half* Or1 = Or0 + (size_t)8 * CH;
#pragma unroll
    for (int nt = 0; nt < 8; nt++) {
        *(__half2*)(Or0 + nt * 8 + 2 * t4) = __floats2half2_rn(o[nt][0] * inv0, o[nt][1] * inv0);
        *(__half2*)(Or1 + nt * 8 + 2 * t4) = __floats2half2_rn(o[nt][2] * inv1, o[nt][3] * inv1);
    }
}

// ---------------------------------------------------------------------------
// Launch: pack fp16 -> gemm1(fp16) -> attention -> gemm2(fp16)
// ---------------------------------------------------------------------------
extern "C" void kernel_launch(void* const* d_in, const int* in_sizes, int n_in,
                              void* d_out, int out_size)
{
    const float* x      = (const float*)d_in[0];
    const float* qkv_w  = (const float*)d_in[1];
    const float* qkv_b  = (const float*)d_in[2];
    const float* proj_w = (const float*)d_in[3];
    const float* proj_b = (const float*)d_in[4];
    float* out = (float*)d_out;

    float* qkvbuf;
    __half *xh, *wqh, *wph, *ath;
    cudaGetSymbolAddress((void**)&qkvbuf, g_qkv);
    cudaGetSymbolAddress((void**)&xh,  g_xh);
    cudaGetSymbolAddress((void**)&wqh, g_wqh);
    cudaGetSymbolAddress((void**)&wph, g_wph);
    cudaGetSymbolAddress((void**)&ath, g_ath);

    cudaFuncSetAttribute(attn_tc, cudaFuncAttributeMaxDynamicSharedMemorySize,
                         (int)sizeof(AttnSmem));

    // Pre-pass: fp32 -> fp16
    pack_half<<<(MROWS * CH / 4 + 255) / 256, 256>>>(x, xh, MROWS * CH / 4);
    pack_half<<<(QKVC  * CH / 4 + 255) / 256, 256>>>(qkv_w, wqh, QKVC * CH / 4);
    pack_half<<<(CH    * CH / 4 + 255) / 256, 256>>>(proj_w, wph, CH * CH / 4);

    // 1) qkv = x @ qkv_w^T + qkv_b   (M=18432, N=2304, K=768)
    dim3 g1(QKVC / 128, MROWS / 128);    // (18, 144)
    gemm_fp16<<<g1, 256>>>(xh, wqh, qkv_b, qkvbuf, QKVC, CH);

    // 2) block-causal attention -> fp16
    dim3 g2(SEQ / 64, NH, BATCH);        // (9, 12, 32)
    attn_tc<<<g2, 128, (int)sizeof(AttnSmem)>>>(qkvbuf, ath);

    // 3) out = att @ proj_w^T + proj_b  (M=18432, N=768, K=768)
    dim3 g3(CH / 128, MROWS / 128);      // (6, 144)
    gemm_fp16<<<g3, 256>>>(ath, wph, proj_b, out, CH, CH);
}

// round 7
// speedup vs baseline: 2.0688x; 1.2408x over previous
#include <cuda_runtime.h>
#include <cuda_fp16.h>
#include <cstdint>

// Problem constants
#define BATCH 32
#define SEQ   576
#define CH    768
#define NH    12
#define HD    64
#define MROWS (BATCH * SEQ)      // 18432
#define QKVC  (3 * CH)           // 2304
#define GRID24 24
#define BS4   4

// ---------------------------------------------------------------------------
// Scratch (__device__ globals; no allocations allowed)
// ---------------------------------------------------------------------------
__device__ float  g_q  [(size_t)MROWS * CH];     // Q fp32 (gemm1 out, sec 0)
__device__ __half g_kh [(size_t)MROWS * CH];     // K hi fp16 (sec 1)
__device__ __half g_kl [(size_t)MROWS * CH];     // K lo fp16 (sec 1)
__device__ __half g_vh [(size_t)MROWS * CH];     // V fp16 (sec 2)
__device__ __half g_xh [(size_t)MROWS * CH];     // x fp16
__device__ __half g_wqh[(size_t)QKVC * CH];      // qkv_w fp16
__device__ __half g_wph[(size_t)CH * CH];        // proj_w fp16
__device__ __half g_ath[(size_t)MROWS * CH];     // attention out fp16

__device__ __forceinline__ int block_idx_of(int p) {
    int i = p / GRID24;
    int j = p - i * GRID24;
    return (i >> 2) * (GRID24 / BS4) + (j >> 2);
}

// ---------------------------------------------------------------------------
// helpers
// ---------------------------------------------------------------------------
__device__ __forceinline__ void cp_async16(void* smem, const void* gmem) {
    uint32_t s = (uint32_t)__cvta_generic_to_shared(smem);
    asm volatile("cp.async.cg.shared.global [%0], [%1], 16;\n" :: "r"(s), "l"(gmem));
}
__device__ __forceinline__ void cp_commit() {
    asm volatile("cp.async.commit_group;\n");
}
template<int N>
__device__ __forceinline__ void cp_wait() {
    asm volatile("cp.async.wait_group %0;\n" :: "n"(N));
}
__device__ __forceinline__ uint32_t smem_u32(const void* p) {
    uint32_t a;
    asm("{ .reg .u64 t; cvta.to.shared.u64 t, %1; cvt.u32.u64 %0, t; }" : "=r"(a) : "l"(p));
    return a;
}
#define LDMATRIX_X4(r0, r1, r2, r3, addr)                                       \
    asm volatile("ldmatrix.sync.aligned.m8n8.x4.shared.b16 {%0,%1,%2,%3}, [%4];" \
                 : "=r"(r0), "=r"(r1), "=r"(r2), "=r"(r3) : "r"(addr))
#define LDMATRIX_X4_T(r0, r1, r2, r3, addr)                                     \
    asm volatile("ldmatrix.sync.aligned.m8n8.x4.trans.shared.b16 {%0,%1,%2,%3}, [%4];" \
                 : "=r"(r0), "=r"(r1), "=r"(r2), "=r"(r3) : "r"(addr))

#define MMA_F16(acc, a0,a1,a2,a3, b0,b1)                                        \
    asm volatile(                                                               \
        "mma.sync.aligned.m16n8k16.row.col.f32.f16.f16.f32 "                    \
        "{%0,%1,%2,%3}, {%4,%5,%6,%7}, {%8,%9}, {%0,%1,%2,%3};\n"               \
        : "+f"(acc[0]), "+f"(acc[1]), "+f"(acc[2]), "+f"(acc[3])                \
        : "r"(a0), "r"(a1), "r"(a2), "r"(a3), "r"(b0), "r"(b1))

// Fast exp on FMA pipe
__device__ __forceinline__ float fexp(float x) {
    x = fmaxf(x, -87.0f);
    float t = x * 1.44269504f;
    int   ei = __float2int_rn(t);
    float fn = (float)ei;
    float r  = fmaf(fn, -0.69314718f, x);
    float p  = 8.3333337e-3f;
    p = fmaf(p, r, 4.1666668e-2f);
    p = fmaf(p, r, 0.16666667f);
    p = fmaf(p, r, 0.5f);
    p = fmaf(p, r, 1.0f);
    p = fmaf(p, r, 1.0f);
    return p * __int_as_float((ei + 127) << 23);
}

__device__ __forceinline__ uint32_t pack_h2(__half2 h) { return *(uint32_t*)&h; }

// ---------------------------------------------------------------------------
// Pre-pass: fp32 row-major -> fp16 row-major
// ---------------------------------------------------------------------------
__global__ void pack_half(const float* __restrict__ src, __half* __restrict__ dst,
                          int total4)
{
    int idx = blockIdx.x * blockDim.x + threadIdx.x;
    if (idx >= total4) return;
    float4 f = *(const float4*)(src + (size_t)idx * 4);
    ((__half2*)dst)[idx * 2]     = __floats2half2_rn(f.x, f.y);
    ((__half2*)dst)[idx * 2 + 1] = __floats2half2_rn(f.z, f.w);
}

// ---------------------------------------------------------------------------
// FP16 tensor-core GEMM (NT): C = A @ B^T + bias, K=768.
// 128x128x32 CTA tile, 8 warps, m16n8k16, ldmatrix, double buffer.
// ROUTE=0: plain fp32 store. ROUTE=1: qkv routing (Q fp32 / K hi+lo / V fp16).
// ---------------------------------------------------------------------------
#define BKH 32
#define LDH 40

template<int ROUTE>
__global__ __launch_bounds__(256)
void gemm_fp16(const __half* __restrict__ A, const __half* __restrict__ Bm,
               const float* __restrict__ bias, float* __restrict__ Cm,
               __half* __restrict__ KH, __half* __restrict__ KL,
               __half* __restrict__ VH, int ncols, int Kd)
{
    __shared__ __half As[2][128 * LDH];
    __shared__ __half Bs[2][128 * LDH];

    const int tid  = threadIdx.x;
    const int wid  = tid >> 5;
    const int lane = tid & 31;
    const int g    = lane >> 2;
    const int t4   = lane & 3;
    const int wm   = (wid & 3) * 32;
    const int wn   = (wid >> 2) * 64;
    const int bx = blockIdx.x, by = blockIdx.y;

    const __half* Ag = A  + (size_t)(by * 128) * Kd;
    const __half* Bg = Bm + (size_t)(bx * 128) * Kd;

    float acc[2][8][4];
#pragma unroll
    for (int mt = 0; mt < 2; mt++)
#pragma unroll
        for (int nt = 0; nt < 8; nt++)
#pragma unroll
            for (int r = 0; r < 4; r++) acc[mt][nt][r] = 0.f;

    const int a_row = (lane & 7) + ((lane >> 3) & 1) * 8;
    const int a_ch  = ((lane >> 4) & 1) * 8;
    const int b_row = (lane & 7) + ((lane >> 4) & 1) * 8;
    const int b_ch  = ((lane >> 3) & 1) * 8;

    const int nk = Kd / BKH;

    auto issue = [&](int kt, int s) {
        const int k0 = kt * BKH;
#pragma unroll
        for (int i = 0; i < 2; i++) {
            int fi = tid + (i << 8);
            int r  = fi >> 2;
            int c  = (fi & 3) << 3;
            cp_async16(&As[s][r * LDH + c], Ag + (size_t)r * Kd + k0 + c);
            cp_async16(&Bs[s][r * LDH + c], Bg + (size_t)r * Kd + k0 + c);
        }
        cp_commit();
    };

    issue(0, 0);

    for (int kt = 0; kt < nk; kt++) {
        const int s = kt & 1;
        if (kt + 1 < nk) {
            issue(kt + 1, s ^ 1);
            cp_wait<1>();
        } else {
            cp_wait<0>();
        }
        __syncthreads();

#pragma unroll
        for (int kk = 0; kk < 2; kk++) {
            const int k0 = kk * 16;
            uint32_t af[2][4];
#pragma unroll
            for (int mt = 0; mt < 2; mt++) {
                uint32_t addr = smem_u32(&As[s][(wm + mt * 16 + a_row) * LDH + k0 + a_ch]);
                LDMATRIX_X4(af[mt][0], af[mt][1], af[mt][2], af[mt][3], addr);
            }
#pragma unroll
            for (int np = 0; np < 4; np++) {
                uint32_t b0, b1, b2, b3;
                uint32_t addr = smem_u32(&Bs[s][(wn + np * 16 + b_row) * LDH + k0 + b_ch]);
                LDMATRIX_X4(b0, b1, b2, b3, addr);
#pragma unroll
                for (int mt = 0; mt < 2; mt++) {
                    MMA_F16(acc[mt][np * 2],     af[mt][0], af[mt][1], af[mt][2], af[mt][3], b0, b1);
                    MMA_F16(acc[mt][np * 2 + 1], af[mt][0], af[mt][1], af[mt][2], af[mt][3], b2, b3);
                }
            }
        }
        __syncthreads();
    }

    // Epilogue
    if (ROUTE == 0) {
#pragma unroll
        for (int mt = 0; mt < 2; mt++) {
            const int row = by * 128 + wm + mt * 16 + g;
#pragma unroll
            for (int nt = 0; nt < 8; nt++) {
                const int col = bx * 128 + wn + nt * 8 + (t4 << 1);
                float bx0 = bias[col], bx1 = bias[col + 1];
                float2 v0, v1;
                v0.x = acc[mt][nt][0] + bx0; v0.y = acc[mt][nt][1] + bx1;
                v1.x = acc[mt][nt][2] + bx0; v1.y = acc[mt][nt][3] + bx1;
                *(float2*)(Cm + (size_t)row * ncols + col)       = v0;
                *(float2*)(Cm + (size_t)(row + 8) * ncols + col) = v1;
            }
        }
    } else {
        const int sec = bx / 6;                 // 0=Q, 1=K, 2=V
        const int cb  = bx * 128 - sec * 768;   // col base within section
#pragma unroll
        for (int mt = 0; mt < 2; mt++) {
            const int row = by * 128 + wm + mt * 16 + g;
#pragma unroll
            for (int nt = 0; nt < 8; nt++) {
                const int colr = cb + wn + nt * 8 + (t4 << 1);
                const int colg = sec * 768 + colr;
                float bx0 = bias[colg], bx1 = bias[colg + 1];
                float r0 = acc[mt][nt][0] + bx0, r1 = acc[mt][nt][1] + bx1;
                float r2 = acc[mt][nt][2] + bx0, r3 = acc[mt][nt][3] + bx1;
                if (sec == 0) {
                    float2 v0; v0.x = r0; v0.y = r1;
                    float2 v1; v1.x = r2; v1.y = r3;
                    *(float2*)(Cm + (size_t)row * CH + colr)       = v0;
                    *(float2*)(Cm + (size_t)(row + 8) * CH + colr) = v1;
                } else if (sec == 1) {
                    __half2 h0 = __floats2half2_rn(r0, r1);
                    __half2 h1 = __floats2half2_rn(r2, r3);
                    float2 f0 = __half22float2(h0), f1 = __half22float2(h1);
                    __half2 l0 = __floats2half2_rn(r0 - f0.x, r1 - f0.y);
                    __half2 l1 = __floats2half2_rn(r2 - f1.x, r3 - f1.y);
                    *(__half2*)(KH + (size_t)row * CH + colr)       = h0;
                    *(__half2*)(KH + (size_t)(row + 8) * CH + colr) = h1;
                    *(__half2*)(KL + (size_t)row * CH + colr)       = l0;
                    *(__half2*)(KL + (size_t)(row + 8) * CH + colr) = l1;
                } else {
                    *(__half2*)(VH + (size_t)row * CH + colr)       = __floats2half2_rn(r0, r1);
                    *(__half2*)(VH + (size_t)(row + 8) * CH + colr) = __floats2half2_rn(r2, r3);
                }
            }
        }
    }
}

// ---------------------------------------------------------------------------
// FP16 tensor-core block-causal flash attention.
// Block = (qt, h, b): 64 q-rows, 4 warps x 16 rows. K-tiles of 64 keys.
// QK^T: 3-term fp16 split (qh*kh + qh*kl + ql*kh). Softmax: poly exp.
// PV: register-direct P fragments + ldmatrix.trans V. No smem roundtrip.
// ---------------------------------------------------------------------------
#define LDK 72

__global__ __launch_bounds__(128)
void attn_fp16(const float* __restrict__ Qf,
               const __half* __restrict__ Kh, const __half* __restrict__ Kl,
               const __half* __restrict__ Vh, __half* __restrict__ atth)
{
    __shared__ __half sKh[64 * LDK];
    __shared__ __half sKl[64 * LDK];
    __shared__ __half sV [64 * LDK];
    __shared__ int    kbi[SEQ];
    __shared__ int    kmin[9];
    __shared__ int    smaxbq;

    const int b = blockIdx.z, h = blockIdx.y, qt = blockIdx.x;
    const int tid = threadIdx.x, wid = tid >> 5, lane = tid & 31;
    const int g = lane >> 2, t4 = lane & 3;
    const int wm = wid * 16;

    for (int p = tid; p < SEQ; p += 128) kbi[p] = block_idx_of(p);
    __syncthreads();
    if (tid < 9) {
        int mn = 1 << 30;
        for (int j = 0; j < 64; j++) mn = min(mn, kbi[tid * 64 + j]);
        kmin[tid] = mn;
    } else if (tid == 9) {
        int mx = -1;
        for (int j = 0; j < 64; j++) mx = max(mx, kbi[qt * 64 + j]);
        smaxbq = mx;
    }
    __syncthreads();

    const int qr0 = qt * 64 + wm + g;
    const int bq0 = kbi[qr0];
    const int bq1 = kbi[qr0 + 8];
    const int maxbq = smaxbq;

    // Q fragments (A operand m16n8k16), pre-scaled by 1/8, fp16 hi/lo split
    uint32_t qh[4][4], ql[4][4];
    {
        const float* Qp0 = Qf + (size_t)(b * SEQ + qr0) * CH + h * HD;
        const float* Qp1 = Qp0 + (size_t)8 * CH;
#pragma unroll
        for (int kc = 0; kc < 4; kc++) {
            float2 x00 = *(const float2*)(Qp0 + kc * 16 + 2 * t4);
            float2 x10 = *(const float2*)(Qp1 + kc * 16 + 2 * t4);
            float2 x01 = *(const float2*)(Qp0 + kc * 16 + 8 + 2 * t4);
            float2 x11 = *(const float2*)(Qp1 + kc * 16 + 8 + 2 * t4);
            x00.x *= 0.125f; x00.y *= 0.125f; x10.x *= 0.125f; x10.y *= 0.125f;
            x01.x *= 0.125f; x01.y *= 0.125f; x11.x *= 0.125f; x11.y *= 0.125f;
            __half2 h0 = __floats2half2_rn(x00.x, x00.y);
            __half2 h1 = __floats2half2_rn(x10.x, x10.y);
            __half2 h2 = __floats2half2_rn(x01.x, x01.y);
            __half2 h3 = __floats2half2_rn(x11.x, x11.y);
            float2 f0 = __half22float2(h0), f1 = __half22float2(h1);
            float2 f2 = __half22float2(h2), f3 = __half22float2(h3);
            qh[kc][0] = pack_h2(h0); ql[kc][0] = pack_h2(__floats2half2_rn(x00.x - f0.x, x00.y - f0.y));
            qh[kc][1] = pack_h2(h1); ql[kc][1] = pack_h2(__floats2half2_rn(x10.x - f1.x, x10.y - f1.y));
            qh[kc][2] = pack_h2(h2); ql[kc][2] = pack_h2(__floats2half2_rn(x01.x - f2.x, x01.y - f2.y));
            qh[kc][3] = pack_h2(h3); ql[kc][3] = pack_h2(__floats2half2_rn(x11.x - f3.x, x11.y - f3.y));
        }
    }

    float m0 = -1e30f, m1 = -1e30f, l0 = 0.f, l1 = 0.f;
    float o[8][4];
#pragma unroll
    for (int nt = 0; nt < 8; nt++)
#pragma unroll
        for (int r = 0; r < 4; r++) o[nt][r] = 0.f;

    // ldmatrix lane address components
    const int b_row = (lane & 7) + ((lane >> 4) & 1) * 8;   // non-trans (K)
    const int b_ch  = ((lane >> 3) & 1) * 8;
    const int t_row = (lane & 7) + ((lane >> 3) & 1) * 8;   // trans (V)
    const int t_ch  = ((lane >> 4) & 1) * 8;

    for (int kt = 0; kt < 9; kt++) {
        if (kmin[kt] > maxbq) continue;
        __syncthreads();

        // cp.async K hi/lo + V tiles (64 x 64 half each)
        {
            const __half* Kgh = Kh + (size_t)(b * SEQ + kt * 64) * CH + h * HD;
            const __half* Kgl = Kl + (size_t)(b * SEQ + kt * 64) * CH + h * HD;
            const __half* Vg  = Vh + (size_t)(b * SEQ + kt * 64) * CH + h * HD;
#pragma unroll
            for (int i = 0; i < 4; i++) {
                int u = tid + i * 128;
                int r = u >> 3, c = (u & 7) << 3;
                cp_async16(&sKh[r * LDK + c], Kgh + (size_t)r * CH + c);
                cp_async16(&sKl[r * LDK + c], Kgl + (size_t)r * CH + c);
                cp_async16(&sV [r * LDK + c], Vg  + (size_t)r * CH + c);
            }
            cp_commit();
            cp_wait<0>();
        }
        __syncthreads();

        // S = Q K^T (3-term fp16 split)
        float sacc[8][4];
#pragma unroll
        for (int nt = 0; nt < 8; nt++)
#pragma unroll
            for (int r = 0; r < 4; r++) sacc[nt][r] = 0.f;

#pragma unroll
        for (int kc = 0; kc < 4; kc++) {
            const int k0 = kc * 16;
#pragma unroll
            for (int np = 0; np < 4; np++) {
                uint32_t h0, h1, h2, h3, lo0, lo1, lo2, lo3;
                uint32_t ah = smem_u32(&sKh[(np * 16 + b_row) * LDK + k0 + b_ch]);
                uint32_t al = smem_u32(&sKl[(np * 16 + b_row) * LDK + k0 + b_ch]);
                LDMATRIX_X4(h0, h1, h2, h3, ah);
                LDMATRIX_X4(lo0, lo1, lo2, lo3, al);
                MMA_F16(sacc[np * 2],     qh[kc][0], qh[kc][1], qh[kc][2], qh[kc][3], h0, h1);
                MMA_F16(sacc[np * 2 + 1], qh[kc][0], qh[kc][1], qh[kc][2], qh[kc][3], h2, h3);
                MMA_F16(sacc[np * 2],     qh[kc][0], qh[kc][1], qh[kc][2], qh[kc][3], lo0, lo1);
                MMA_F16(sacc[np * 2 + 1], qh[kc][0], qh[kc][1], qh[kc][2], qh[kc][3], lo2, lo3);
                MMA_F16(sacc[np * 2],     ql[kc][0], ql[kc][1], ql[kc][2], ql[kc][3], h0, h1);
                MMA_F16(sacc[np * 2 + 1], ql[kc][0], ql[kc][1], ql[kc][2], ql[kc][3], h2, h3);
            }
        }

        // Mask
        const int c0 = kt * 64;
#pragma unroll
        for (int nt = 0; nt < 8; nt++) {
            int k0b = kbi[c0 + nt * 8 + 2 * t4];
            int k1b = kbi[c0 + nt * 8 + 2 * t4 + 1];
            if (k0b > bq0) sacc[nt][0] = -1e30f;
            if (k1b > bq0) sacc[nt][1] = -1e30f;
            if (k0b > bq1) sacc[nt][2] = -1e30f;
            if (k1b > bq1) sacc[nt][3] = -1e30f;
        }

        // Row max
        float mx0 = -1e30f, mx1 = -1e30f;
#pragma unroll
        for (int nt = 0; nt < 8; nt++) {
            mx0 = fmaxf(mx0, fmaxf(sacc[nt][0], sacc[nt][1]));
            mx1 = fmaxf(mx1, fmaxf(sacc[nt][2], sacc[nt][3]));
        }
        mx0 = fmaxf(mx0, __shfl_xor_sync(0xffffffffu, mx0, 1));
        mx0 = fmaxf(mx0, __shfl_xor_sync(0xffffffffu, mx0, 2));
        mx1 = fmaxf(mx1, __shfl_xor_sync(0xffffffffu, mx1, 1));
        mx1 = fmaxf(mx1, __shfl_xor_sync(0xffffffffu, mx1, 2));

        float nm0 = fmaxf(m0, mx0), nm1 = fmaxf(m1, mx1);
        float cr0 = fexp(m0 - nm0), cr1 = fexp(m1 - nm1);
        m0 = nm0; m1 = nm1;
        l0 *= cr0; l1 *= cr1;
#pragma unroll
        for (int nt = 0; nt < 8; nt++) {
            o[nt][0] *= cr0; o[nt][1] *= cr0;
            o[nt][2] *= cr1; o[nt][3] *= cr1;
        }

        // p = exp(s - m) -> fp16 fragments (register-direct A operand for PV)
        uint32_t pa[4][4];
        float s0 = 0.f, s1 = 0.f;
#pragma unroll
        for (int nt = 0; nt < 8; nt++) {
            float p0 = (sacc[nt][0] > -1e29f) ? fexp(sacc[nt][0] - nm0) : 0.f;
            float p1 = (sacc[nt][1] > -1e29f) ? fexp(sacc[nt][1] - nm0) : 0.f;
            float p2 = (sacc[nt][2] > -1e29f) ? fexp(sacc[nt][2] - nm1) : 0.f;
            float p3 = (sacc[nt][3] > -1e29f) ? fexp(sacc[nt][3] - nm1) : 0.f;
            __half2 h01 = __floats2half2_rn(p0, p1);   // row g
            __half2 h23 = __floats2half2_rn(p2, p3);   // row g+8
            float2 f01 = __half22float2(h01), f23 = __half22float2(h23);
            s0 += f01.x + f01.y; s1 += f23.x + f23.y;
            int kc2 = nt >> 1, hi = (nt & 1) << 1;
            pa[kc2][hi]     = pack_h2(h01);
            pa[kc2][hi + 1] = pack_h2(h23);
        }
        s0 += __shfl_xor_sync(0xffffffffu, s0, 1);
        s0 += __shfl_xor_sync(0xffffffffu, s0, 2);
        s1 += __shfl_xor_sync(0xffffffffu, s1, 1);
        s1 += __shfl_xor_sync(0xffffffffu, s1, 2);
        l0 += s0; l1 += s1;

        // O += P @ V (V via ldmatrix.trans)
#pragma unroll
        for (int kc2 = 0; kc2 < 4; kc2++) {
#pragma unroll
            for (int dp = 0; dp < 4; dp++) {
                uint32_t v0, v1, v2, v3;
                uint32_t addr = smem_u32(&sV[(kc2 * 16 + t_row) * LDK + dp * 16 + t_ch]);
                LDMATRIX_X4_T(v0, v1, v2, v3, addr);
                MMA_F16(o[dp * 2],     pa[kc2][0], pa[kc2][1], pa[kc2][2], pa[kc2][3], v0, v1);
                MMA_F16(o[dp * 2 + 1], pa[kc2][0], pa[kc2][1], pa[kc2][2], pa[kc2][3], v2, v3);
            }
        }
    }

    // Epilogue: normalize + store fp16 (feeds GEMM2)
    const float inv0 = 1.f / l0, inv1 = 1.f / l1;
    __half* Or0 = atth + (size_t)(b * SEQ + qr0) * CH + h * HD;
    __half* Or1 = Or0 + (size_t)8 * CH;
#pragma unroll
    for (int nt = 0; nt < 8; nt++) {
        *(__half2*)(Or0 + nt * 8 + 2 * t4) = __floats2half2_rn(o[nt][0] * inv0, o[nt][1] * inv0);
        *(__half2*)(Or1 + nt * 8 + 2 * t4) = __floats2half2_rn(o[nt][2] * inv1, o[nt][3] * inv1);
    }
}

// ---------------------------------------------------------------------------
// Launch
// ---------------------------------------------------------------------------
extern "C" void kernel_launch(void* const* d_in, const int* in_sizes, int n_in,
                              void* d_out, int out_size)
{
    const float* x      = (const float*)d_in[0];
    const float* qkv_w  = (const float*)d_in[1];
    const float* qkv_b  = (const float*)d_in[2];
    const float* proj_w = (const float*)d_in[3];
    const float* proj_b = (const float*)d_in[4];
    float* out = (float*)d_out;

    float* qbuf;
    __half *khb, *klb, *vhb, *xh, *wqh, *wph, *ath;
    cudaGetSymbolAddress((void**)&qbuf, g_q);
    cudaGetSymbolAddress((void**)&khb, g_kh);
    cudaGetSymbolAddress((void**)&klb, g_kl);
    cudaGetSymbolAddress((void**)&vhb, g_vh);
    cudaGetSymbolAddress((void**)&xh,  g_xh);
    cudaGetSymbolAddress((void**)&wqh, g_wqh);
    cudaGetSymbolAddress((void**)&wph, g_wph);
    cudaGetSymbolAddress((void**)&ath, g_ath);

    // Pre-pass: fp32 -> fp16
    pack_half<<<(MROWS * CH / 4 + 255) / 256, 256>>>(x, xh, MROWS * CH / 4);
    pack_half<<<(QKVC  * CH / 4 + 255) / 256, 256>>>(qkv_w, wqh, QKVC * CH / 4);
    pack_half<<<(CH    * CH / 4 + 255) / 256, 256>>>(proj_w, wph, CH * CH / 4);

    // 1) qkv = x @ qkv_w^T + qkv_b, routed: Q fp32 / K hi+lo / V fp16
    dim3 g1(QKVC / 128, MROWS / 128);    // (18, 144)
    gemm_fp16<1><<<g1, 256>>>(xh, wqh, qkv_b, qbuf, khb, klb, vhb, CH, CH);

    // 2) fp16 block-causal flash attention
    dim3 g2(SEQ / 64, NH, BATCH);        // (9, 12, 32)
    attn_fp16<<<g2, 128>>>(qbuf, khb, klb, vhb, ath);

    // 3) out = att @ proj_w^T + proj_b
    dim3 g3(CH / 128, MROWS / 128);      // (6, 144)
    gemm_fp16<0><<<g3, 256>>>(ath, wph, proj_b, out, nullptr, nullptr, nullptr, CH, CH);
}

// round 10
// speedup vs baseline: 2.3813x; 1.1510x over previous
#include <cuda_runtime.h>
#include <cuda_fp16.h>
#include <cstdint>

// Problem constants
#define BATCH 32
#define SEQ   576
#define CH    768
#define NH    12
#define HD    64
#define MROWS (BATCH * SEQ)      // 18432
#define QKVC  (3 * CH)           // 2304
#define GRID24 24
#define BS4   4

// ---------------------------------------------------------------------------
// Scratch (__device__ globals; no allocations allowed)
// ---------------------------------------------------------------------------
__device__ float  g_q  [(size_t)MROWS * CH];     // Q fp32 (gemm1 out, sec 0)
__device__ __half g_kh [(size_t)MROWS * CH];     // K hi fp16 (sec 1)
__device__ __half g_kl [(size_t)MROWS * CH];     // K lo fp16 (sec 1)
__device__ __half g_vh [(size_t)MROWS * CH];     // V fp16 (sec 2)
__device__ __half g_xh [(size_t)MROWS * CH];     // x fp16
__device__ __half g_wqh[(size_t)QKVC * CH];      // qkv_w fp16
__device__ __half g_wph[(size_t)CH * CH];        // proj_w fp16
__device__ __half g_ath[(size_t)MROWS * CH];     // attention out fp16

__device__ __forceinline__ int block_idx_of(int p) {
    int i = p / GRID24;
    int j = p - i * GRID24;
    return (i >> 2) * (GRID24 / BS4) + (j >> 2);
}

// ---------------------------------------------------------------------------
// helpers
// ---------------------------------------------------------------------------
__device__ __forceinline__ void cp_async16(void* smem, const void* gmem) {
    uint32_t s = (uint32_t)__cvta_generic_to_shared(smem);
    asm volatile("cp.async.cg.shared.global [%0], [%1], 16;\n" :: "r"(s), "l"(gmem));
}
__device__ __forceinline__ void cp_commit() {
    asm volatile("cp.async.commit_group;\n");
}
template<int N>
__device__ __forceinline__ void cp_wait() {
    asm volatile("cp.async.wait_group %0;\n" :: "n"(N));
}
__device__ __forceinline__ uint32_t smem_u32(const void* p) {
    uint32_t a;
    asm("{ .reg .u64 t; cvta.to.shared.u64 t, %1; cvt.u32.u64 %0, t; }" : "=r"(a) : "l"(p));
    return a;
}
#define LDMATRIX_X4(r0, r1, r2, r3, addr)                                       \
    asm volatile("ldmatrix.sync.aligned.m8n8.x4.shared.b16 {%0,%1,%2,%3}, [%4];" \
                 : "=r"(r0), "=r"(r1), "=r"(r2), "=r"(r3) : "r"(addr))
#define LDMATRIX_X4_T(r0, r1, r2, r3, addr)                                     \
    asm volatile("ldmatrix.sync.aligned.m8n8.x4.trans.shared.b16 {%0,%1,%2,%3}, [%4];" \
                 : "=r"(r0), "=r"(r1), "=r"(r2), "=r"(r3) : "r"(addr))

#define MMA_F16(acc, a0,a1,a2,a3, b0,b1)                                        \
    asm volatile(                                                               \
        "mma.sync.aligned.m16n8k16.row.col.f32.f16.f16.f32 "                    \
        "{%0,%1,%2,%3}, {%4,%5,%6,%7}, {%8,%9}, {%0,%1,%2,%3};\n"               \
        : "+f"(acc[0]), "+f"(acc[1]), "+f"(acc[2]), "+f"(acc[3])                \
        : "r"(a0), "r"(a1), "r"(a2), "r"(a3), "r"(b0), "r"(b1))

// Fast exp on FMA pipe
__device__ __forceinline__ float fexp(float x) {
    x = fmaxf(x, -87.0f);
    float t = x * 1.44269504f;
    int   ei = __float2int_rn(t);
    float fn = (float)ei;
    float r  = fmaf(fn, -0.69314718f, x);
    float p  = 8.3333337e-3f;
    p = fmaf(p, r, 4.1666668e-2f);
    p = fmaf(p, r, 0.16666667f);
    p = fmaf(p, r, 0.5f);
    p = fmaf(p, r, 1.0f);
    p = fmaf(p, r, 1.0f);
    return p * __int_as_float((ei + 127) << 23);
}

__device__ __forceinline__ uint32_t pack_h2(__half2 h) { return *(uint32_t*)&h; }

// ---------------------------------------------------------------------------
// Pre-pass: fp32 row-major -> fp16 row-major
// ---------------------------------------------------------------------------
__global__ void pack_half(const float* __restrict__ src, __half* __restrict__ dst,
                          int total4)
{
    int idx = blockIdx.x * blockDim.x + threadIdx.x;
    if (idx >= total4) return;
    float4 f = *(const float4*)(src + (size_t)idx * 4);
    ((__half2*)dst)[idx * 2]     = __floats2half2_rn(f.x, f.y);
    ((__half2*)dst)[idx * 2 + 1] = __floats2half2_rn(f.z, f.w);
}

// ---------------------------------------------------------------------------
// FP16 tensor-core GEMM (NT) — unchanged from R6 (at mma.sync issue floor).
// ---------------------------------------------------------------------------
#define BKH 32
#define LDH 40

template<int ROUTE>
__global__ __launch_bounds__(256)
void gemm_fp16(const __half* __restrict__ A, const __half* __restrict__ Bm,
               const float* __restrict__ bias, float* __restrict__ Cm,
               __half* __restrict__ KH, __half* __restrict__ KL,
               __half* __restrict__ VH, int ncols, int Kd)
{
    __shared__ __half As[2][128 * LDH];
    __shared__ __half Bs[2][128 * LDH];

    const int tid  = threadIdx.x;
    const int wid  = tid >> 5;
    const int lane = tid & 31;
    const int g    = lane >> 2;
    const int t4   = lane & 3;
    const int wm   = (wid & 3) * 32;
    const int wn   = (wid >> 2) * 64;
    const int bx = blockIdx.x, by = blockIdx.y;

    const __half* Ag = A  + (size_t)(by * 128) * Kd;
    const __half* Bg = Bm + (size_t)(bx * 128) * Kd;

    float acc[2][8][4];
#pragma unroll
    for (int mt = 0; mt < 2; mt++)
#pragma unroll
        for (int nt = 0; nt < 8; nt++)
#pragma unroll
            for (int r = 0; r < 4; r++) acc[mt][nt][r] = 0.f;

    const int a_row = (lane & 7) + ((lane >> 3) & 1) * 8;
    const int a_ch  = ((lane >> 4) & 1) * 8;
    const int b_row = (lane & 7) + ((lane >> 4) & 1) * 8;
    const int b_ch  = ((lane >> 3) & 1) * 8;

    const int nk = Kd / BKH;

    auto issue = [&](int kt, int s) {
        const int k0 = kt * BKH;
#pragma unroll
        for (int i = 0; i < 2; i++) {
            int fi = tid + (i << 8);
            int r  = fi >> 2;
            int c  = (fi & 3) << 3;
            cp_async16(&As[s][r * LDH + c], Ag + (size_t)r * Kd + k0 + c);
            cp_async16(&Bs[s][r * LDH + c], Bg + (size_t)r * Kd + k0 + c);
        }
        cp_commit();
    };

    issue(0, 0);

    for (int kt = 0; kt < nk; kt++) {
        const int s = kt & 1;
        if (kt + 1 < nk) {
            issue(kt + 1, s ^ 1);
            cp_wait<1>();
        } else {
            cp_wait<0>();
        }
        __syncthreads();

#pragma unroll
        for (int kk = 0; kk < 2; kk++) {
            const int k0 = kk * 16;
            uint32_t af[2][4];
#pragma unroll
            for (int mt = 0; mt < 2; mt++) {
                uint32_t addr = smem_u32(&As[s][(wm + mt * 16 + a_row) * LDH + k0 + a_ch]);
                LDMATRIX_X4(af[mt][0], af[mt][1], af[mt][2], af[mt][3], addr);
            }
#pragma unroll
            for (int np = 0; np < 4; np++) {
                uint32_t b0, b1, b2, b3;
                uint32_t addr = smem_u32(&Bs[s][(wn + np * 16 + b_row) * LDH + k0 + b_ch]);
                LDMATRIX_X4(b0, b1, b2, b3, addr);
#pragma unroll
                for (int mt = 0; mt < 2; mt++) {
                    MMA_F16(acc[mt][np * 2],     af[mt][0], af[mt][1], af[mt][2], af[mt][3], b0, b1);
                    MMA_F16(acc[mt][np * 2 + 1], af[mt][0], af[mt][1], af[mt][2], af[mt][3], b2, b3);
                }
            }
        }
        __syncthreads();
    }

    if (ROUTE == 0) {
#pragma unroll
        for (int mt = 0; mt < 2; mt++) {
            const int row = by * 128 + wm + mt * 16 + g;
#pragma unroll
            for (int nt = 0; nt < 8; nt++) {
                const int col = bx * 128 + wn + nt * 8 + (t4 << 1);
                float bx0 = bias[col], bx1 = bias[col + 1];
                float2 v0, v1;
                v0.x = acc[mt][nt][0] + bx0; v0.y = acc[mt][nt][1] + bx1;
                v1.x = acc[mt][nt][2] + bx0; v1.y = acc[mt][nt][3] + bx1;
                *(float2*)(Cm + (size_t)row * ncols + col)       = v0;
                *(float2*)(Cm + (size_t)(row + 8) * ncols + col) = v1;
            }
        }
    } else {
        const int sec = bx / 6;
        const int cb  = bx * 128 - sec * 768;
#pragma unroll
        for (int mt = 0; mt < 2; mt++) {
            const int row = by * 128 + wm + mt * 16 + g;
#pragma unroll
            for (int nt = 0; nt < 8; nt++) {
                const int colr = cb + wn + nt * 8 + (t4 << 1);
                const int colg = sec * 768 + colr;
                float bx0 = bias[colg], bx1 = bias[colg + 1];
                float r0 = acc[mt][nt][0] + bx0, r1 = acc[mt][nt][1] + bx1;
                float r2 = acc[mt][nt][2] + bx0, r3 = acc[mt][nt][3] + bx1;
                if (sec == 0) {
                    float2 v0; v0.x = r0; v0.y = r1;
                    float2 v1; v1.x = r2; v1.y = r3;
                    *(float2*)(Cm + (size_t)row * CH + colr)       = v0;
                    *(float2*)(Cm + (size_t)(row + 8) * CH + colr) = v1;
                } else if (sec == 1) {
                    __half2 h0 = __floats2half2_rn(r0, r1);
                    __half2 h1 = __floats2half2_rn(r2, r3);
                    float2 f0 = __half22float2(h0), f1 = __half22float2(h1);
                    __half2 l0 = __floats2half2_rn(r0 - f0.x, r1 - f0.y);
                    __half2 l1 = __floats2half2_rn(r2 - f1.x, r3 - f1.y);
                    *(__half2*)(KH + (size_t)row * CH + colr)       = h0;
                    *(__half2*)(KH + (size_t)(row + 8) * CH + colr) = h1;
                    *(__half2*)(KL + (size_t)row * CH + colr)       = l0;
                    *(__half2*)(KL + (size_t)(row + 8) * CH + colr) = l1;
                } else {
                    *(__half2*)(VH + (size_t)row * CH + colr)       = __floats2half2_rn(r0, r1);
                    *(__half2*)(VH + (size_t)(row + 8) * CH + colr) = __floats2half2_rn(r2, r3);
                }
            }
        }
    }
}

// ---------------------------------------------------------------------------
// FP16 block-causal flash attention, double-buffered K/V + visibility fast path.
// ---------------------------------------------------------------------------
#define LDK 72
#define KV_TILE_H (64 * LDK)                    // halves per array per stage
#define ATTN_SMEM (2 * 3 * KV_TILE_H * 2 + SEQ * 4 + 4 * 32)

__global__ __launch_bounds__(128)
void attn_fp16(const float* __restrict__ Qf,
               const __half* __restrict__ Kh, const __half* __restrict__ Kl,
               const __half* __restrict__ Vh, __half* __restrict__ atth)
{
    extern __shared__ char smraw[];
    __half* sKh = (__half*)smraw;                        // [2][KV_TILE_H]
    __half* sKl = sKh + 2 * KV_TILE_H;
    __half* sV  = sKl + 2 * KV_TILE_H;
    int* kbi   = (int*)(sV + 2 * KV_TILE_H);             // [SEQ]
    int* kmin  = kbi + SEQ;                              // [9]
    int* kmax  = kmin + 9;                               // [9]
    int* act   = kmax + 9;                               // [9]
    int* meta  = act + 9;                                // [0]=nact, [1]=maxbq, [2]=minbq

    const int b = blockIdx.z, h = blockIdx.y, qt = blockIdx.x;
    const int tid = threadIdx.x, wid = tid >> 5, lane = tid & 31;
    const int g = lane >> 2, t4 = lane & 3;
    const int wm = wid * 16;

    for (int p = tid; p < SEQ; p += 128) kbi[p] = block_idx_of(p);
    __syncthreads();
    if (tid < 9) {
        int mn = 1 << 30, mx = -1;
        for (int j = 0; j < 64; j++) {
            int v = kbi[tid * 64 + j];
            mn = min(mn, v); mx = max(mx, v);
        }
        kmin[tid] = mn; kmax[tid] = mx;
    }
    __syncthreads();
    if (tid == 0) {
        int mxq = kmax[qt], mnq = kmin[qt];
        int n = 0;
        for (int kt = 0; kt < 9; kt++)
            if (kmin[kt] <= mxq) act[n++] = kt;
        meta[0] = n; meta[1] = mxq; meta[2] = mnq;
    }
    __syncthreads();

    const int nact  = meta[0];
    const int minbq = meta[2];
    const int qr0 = qt * 64 + wm + g;
    const int bq0 = kbi[qr0];
    const int bq1 = kbi[qr0 + 8];

    // Q fragments, pre-scaled by 1/8, fp16 hi/lo split
    uint32_t qh[4][4], ql[4][4];
    {
        const float* Qp0 = Qf + (size_t)(b * SEQ + qr0) * CH + h * HD;
        const float* Qp1 = Qp0 + (size_t)8 * CH;
#pragma unroll
        for (int kc = 0; kc < 4; kc++) {
            float2 x00 = *(const float2*)(Qp0 + kc * 16 + 2 * t4);
            float2 x10 = *(const float2*)(Qp1 + kc * 16 + 2 * t4);
            float2 x01 = *(const float2*)(Qp0 + kc * 16 + 8 + 2 * t4);
            float2 x11 = *(const float2*)(Qp1 + kc * 16 + 8 + 2 * t4);
            x00.x *= 0.125f; x00.y *= 0.125f; x10.x *= 0.125f; x10.y *= 0.125f;
            x01.x *= 0.125f; x01.y *= 0.125f; x11.x *= 0.125f; x11.y *= 0.125f;
            __half2 h0 = __floats2half2_rn(x00.x, x00.y);
            __half2 h1 = __floats2half2_rn(x10.x, x10.y);
            __half2 h2 = __floats2half2_rn(x01.x, x01.y);
            __half2 h3 = __floats2half2_rn(x11.x, x11.y);
            float2 f0 = __half22float2(h0), f1 = __half22float2(h1);
            float2 f2 = __half22float2(h2), f3 = __half22float2(h3);
            qh[kc][0] = pack_h2(h0); ql[kc][0] = pack_h2(__floats2half2_rn(x00.x - f0.x, x00.y - f0.y));
            qh[kc][1] = pack_h2(h1); ql[kc][1] = pack_h2(__floats2half2_rn(x10.x - f1.x, x10.y - f1.y));
            qh[kc][2] = pack_h2(h2); ql[kc][2] = pack_h2(__floats2half2_rn(x01.x - f2.x, x01.y - f2.y));
            qh[kc][3] = pack_h2(h3); ql[kc][3] = pack_h2(__floats2half2_rn(x11.x - f3.x, x11.y - f3.y));
        }
    }

    float m0 = -1e30f, m1 = -1e30f, l0 = 0.f, l1 = 0.f;
    float o[8][4];
#pragma unroll
    for (int nt = 0; nt < 8; nt++)
#pragma unroll
        for (int r = 0; r < 4; r++) o[nt][r] = 0.f;

    const int b_row = (lane & 7) + ((lane >> 4) & 1) * 8;
    const int b_ch  = ((lane >> 3) & 1) * 8;
    const int t_row = (lane & 7) + ((lane >> 3) & 1) * 8;
    const int t_ch  = ((lane >> 4) & 1) * 8;

    auto issue_tile = [&](int kt, int s) {
        const __half* Kgh = Kh + (size_t)(b * SEQ + kt * 64) * CH + h * HD;
        const __half* Kgl = Kl + (size_t)(b * SEQ + kt * 64) * CH + h * HD;
        const __half* Vg  = Vh + (size_t)(b * SEQ + kt * 64) * CH + h * HD;
        __half* dKh = sKh + s * KV_TILE_H;
        __half* dKl = sKl + s * KV_TILE_H;
        __half* dV  = sV  + s * KV_TILE_H;
#pragma unroll
        for (int i = 0; i < 4; i++) {
            int u = tid + i * 128;
            int r = u >> 3, c = (u & 7) << 3;
            cp_async16(&dKh[r * LDK + c], Kgh + (size_t)r * CH + c);
            cp_async16(&dKl[r * LDK + c], Kgl + (size_t)r * CH + c);
            cp_async16(&dV [r * LDK + c], Vg  + (size_t)r * CH + c);
        }
        cp_commit();
    };

    issue_tile(act[0], 0);
    if (nact > 1) issue_tile(act[1], 1);

    for (int ia = 0; ia < nact; ia++) {
        const int kt = act[ia];
        const int s  = ia & 1;
        const bool fullvis = (kmax[kt] <= minbq);

        if (ia + 1 < nact) cp_wait<1>(); else cp_wait<0>();
        __syncthreads();

        const __half* cKh = sKh + s * KV_TILE_H;
        const __half* cKl = sKl + s * KV_TILE_H;
        const __half* cV  = sV  + s * KV_TILE_H;

        // S = Q K^T (3-term fp16 split)
        float sacc[8][4];
#pragma unroll
        for (int nt = 0; nt < 8; nt++)
#pragma unroll
            for (int r = 0; r < 4; r++) sacc[nt][r] = 0.f;

#pragma unroll
        for (int kc = 0; kc < 4; kc++) {
            const int k0 = kc * 16;
#pragma unroll
            for (int np = 0; np < 4; np++) {
                uint32_t h0, h1, h2, h3, lo0, lo1, lo2, lo3;
                uint32_t ah = smem_u32(&cKh[(np * 16 + b_row) * LDK + k0 + b_ch]);
                uint32_t al = smem_u32(&cKl[(np * 16 + b_row) * LDK + k0 + b_ch]);
                LDMATRIX_X4(h0, h1, h2, h3, ah);
                LDMATRIX_X4(lo0, lo1, lo2, lo3, al);
                MMA_F16(sacc[np * 2],     qh[kc][0], qh[kc][1], qh[kc][2], qh[kc][3], h0, h1);
                MMA_F16(sacc[np * 2 + 1], qh[kc][0], qh[kc][1], qh[kc][2], qh[kc][3], h2, h3);
                MMA_F16(sacc[np * 2],     qh[kc][0], qh[kc][1], qh[kc][2], qh[kc][3], lo0, lo1);
                MMA_F16(sacc[np * 2 + 1], qh[kc][0], qh[kc][1], qh[kc][2], qh[kc][3], lo2, lo3);
                MMA_F16(sacc[np * 2],     ql[kc][0], ql[kc][1], ql[kc][2], ql[kc][3], h0, h1);
                MMA_F16(sacc[np * 2 + 1], ql[kc][0], ql[kc][1], ql[kc][2], ql[kc][3], h2, h3);
            }
        }

        if (!fullvis) {
            const int c0 = kt * 64;
#pragma unroll
            for (int nt = 0; nt < 8; nt++) {
                int k0b = kbi[c0 + nt * 8 + 2 * t4];
                int k1b = kbi[c0 + nt * 8 + 2 * t4 + 1];
                if (k0b > bq0) sacc[nt][0] = -1e30f;
                if (k1b > bq0) sacc[nt][1] = -1e30f;
                if (k0b > bq1) sacc[nt][2] = -1e30f;
                if (k1b > bq1) sacc[nt][3] = -1e30f;
            }
        }

        // Row max
        float mx0 = -1e30f, mx1 = -1e30f;
#pragma unroll
        for (int nt = 0; nt < 8; nt++) {
            mx0 = fmaxf(mx0, fmaxf(sacc[nt][0], sacc[nt][1]));
            mx1 = fmaxf(mx1, fmaxf(sacc[nt][2], sacc[nt][3]));
        }
        mx0 = fmaxf(mx0, __shfl_xor_sync(0xffffffffu, mx0, 1));
        mx0 = fmaxf(mx0, __shfl_xor_sync(0xffffffffu, mx0, 2));
        mx1 = fmaxf(mx1, __shfl_xor_sync(0xffffffffu, mx1, 1));
        mx1 = fmaxf(mx1, __shfl_xor_sync(0xffffffffu, mx1, 2));

        float nm0 = fmaxf(m0, mx0), nm1 = fmaxf(m1, mx1);
        float cr0 = fexp(m0 - nm0), cr1 = fexp(m1 - nm1);
        m0 = nm0; m1 = nm1;
        l0 *= cr0; l1 *= cr1;
#pragma unroll
        for (int nt = 0; nt < 8; nt++) {
            o[nt][0] *= cr0; o[nt][1] *= cr0;
            o[nt][2] *= cr1; o[nt][3] *= cr1;
        }

        // p = exp(s - m) -> fp16 fragments
        uint32_t pa[4][4];
        float s0 = 0.f, s1 = 0.f;
#pragma unroll
        for (int nt = 0; nt < 8; nt++) {
            float p0, p1, p2, p3;
            if (fullvis) {
                p0 = fexp(sacc[nt][0] - nm0);
                p1 = fexp(sacc[nt][1] - nm0);
                p2 = fexp(sacc[nt][2] - nm1);
                p3 = fexp(sacc[nt][3] - nm1);
            } else {
                p0 = (sacc[nt][0] > -1e29f) ? fexp(sacc[nt][0] - nm0) : 0.f;
                p1 = (sacc[nt][1] > -1e29f) ? fexp(sacc[nt][1] - nm0) : 0.f;
                p2 = (sacc[nt][2] > -1e29f) ? fexp(sacc[nt][2] - nm1) : 0.f;
                p3 = (sacc[nt][3] > -1e29f) ? fexp(sacc[nt][3] - nm1) : 0.f;
            }
            __half2 h01 = __floats2half2_rn(p0, p1);
            __half2 h23 = __floats2half2_rn(p2, p3);
            float2 f01 = __half22float2(h01), f23 = __half22float2(h23);
            s0 += f01.x + f01.y; s1 += f23.x + f23.y;
            int kc2 = nt >> 1, hi = (nt & 1) << 1;
            pa[kc2][hi]     = pack_h2(h01);
            pa[kc2][hi + 1] = pack_h2(h23);
        }
        s0 += __shfl_xor_sync(0xffffffffu, s0, 1);
        s0 += __shfl_xor_sync(0xffffffffu, s0, 2);
        s1 += __shfl_xor_sync(0xffffffffu, s1, 1);
        s1 += __shfl_xor_sync(0xffffffffu, s1, 2);
        l0 += s0; l1 += s1;

        // O += P @ V
#pragma unroll
        for (int kc2 = 0; kc2 < 4; kc2++) {
#pragma unroll
            for (int dp = 0; dp < 4; dp++) {
                uint32_t v0, v1, v2, v3;
                uint32_t addr = smem_u32(&cV[(kc2 * 16 + t_row) * LDK + dp * 16 + t_ch]);
                LDMATRIX_X4_T(v0, v1, v2, v3, addr);
                MMA_F16(o[dp * 2],     pa[kc2][0], pa[kc2][1], pa[kc2][2], pa[kc2][3], v0, v1);
                MMA_F16(o[dp * 2 + 1], pa[kc2][0], pa[kc2][1], pa[kc2][2], pa[kc2][3], v2, v3);
            }
        }

        __syncthreads();                        // all warps done with stage s
        if (ia + 2 < nact) issue_tile(act[ia + 2], s);
    }

    // Epilogue: normalize + store fp16 (feeds GEMM2)
    const float inv0 = 1.f / l0, inv1 = 1.f / l1;
    __half* Or0 = atth + (size_t)(b * SEQ + qr0) * CH + h * HD;
    __half* Or1 = Or0 + (size_t)8 * CH;
#pragma unroll
    for (int nt = 0; nt < 8; nt++) {
        *(__half2*)(Or0 + nt * 8 + 2 * t4) = __floats2half2_rn(o[nt][0] * inv0, o[nt][1] * inv0);
        *(__half2*)(Or1 + nt * 8 + 2 * t4) = __floats2half2_rn(o[nt][2] * inv1, o[nt][3] * inv1);
    }
}

// ---------------------------------------------------------------------------
// Launch
// ---------------------------------------------------------------------------
extern "C" void kernel_launch(void* const* d_in, const int* in_sizes, int n_in,
                              void* d_out, int out_size)
{
    const float* x      = (const float*)d_in[0];
    const float* qkv_w  = (const float*)d_in[1];
    const float* qkv_b  = (const float*)d_in[2];
    const float* proj_w = (const float*)d_in[3];
    const float* proj_b = (const float*)d_in[4];
    float* out = (float*)d_out;

    float* qbuf;
    __half *khb, *klb, *vhb, *xh, *wqh, *wph, *ath;
    cudaGetSymbolAddress((void**)&qbuf, g_q);
    cudaGetSymbolAddress((void**)&khb, g_kh);
    cudaGetSymbolAddress((void**)&klb, g_kl);
    cudaGetSymbolAddress((void**)&vhb, g_vh);
    cudaGetSymbolAddress((void**)&xh,  g_xh);
    cudaGetSymbolAddress((void**)&wqh, g_wqh);
    cudaGetSymbolAddress((void**)&wph, g_wph);
    cudaGetSymbolAddress((void**)&ath, g_ath);

    cudaFuncSetAttribute(attn_fp16, cudaFuncAttributeMaxDynamicSharedMemorySize,
                         ATTN_SMEM);

    // Pre-pass: fp32 -> fp16
    pack_half<<<(MROWS * CH / 4 + 255) / 256, 256>>>(x, xh, MROWS * CH / 4);
    pack_half<<<(QKVC  * CH / 4 + 255) / 256, 256>>>(qkv_w, wqh, QKVC * CH / 4);
    pack_half<<<(CH    * CH / 4 + 255) / 256, 256>>>(proj_w, wph, CH * CH / 4);

    // 1) qkv = x @ qkv_w^T + qkv_b, routed: Q fp32 / K hi+lo / V fp16
    dim3 g1(QKVC / 128, MROWS / 128);    // (18, 144)
    gemm_fp16<1><<<g1, 256>>>(xh, wqh, qkv_b, qbuf, khb, klb, vhb, CH, CH);

    // 2) fp16 block-causal flash attention (double-buffered)
    dim3 g2(SEQ / 64, NH, BATCH);        // (9, 12, 32)
    attn_fp16<<<g2, 128, ATTN_SMEM>>>(qbuf, khb, klb, vhb, ath);

    // 3) out = att @ proj_w^T + proj_b
    dim3 g3(CH / 128, MROWS / 128);      // (6, 144)
    gemm_fp16<0><<<g3, 256>>>(ath, wph, proj_b, out, nullptr, nullptr, nullptr, CH, CH);
}